// round 7
// baseline (speedup 1.0000x reference)
#include <cuda_runtime.h>
#include <cuda_fp16.h>
#include <cuda_fp8.h>
#include <math.h>

#define HID   1024
#define G4    4096
#define NB    32
#define NT    100
#define IND   132
#define KP    192
#define OUTW  13200   // 100*132
#define ASTR  72      // smem fp16 row stride in halves (64+8 pad)
#define DEPTH 5
#define NBLK  129
#define LO_SCALE 16384.0f
#define LO_INV   (1.0f/16384.0f)

// smem byte offsets for the 5-slot ring
#define SM_AH 0          // 5 * 4608  (A hi fp16, 32x72 halves)
#define SM_AL 23040      // 5 * 4608  (A lo fp16)
#define SM_BH 46080      // 5 * 18432 (B hi fp16, 128x72 halves)
#define SM_B8 138240     // 5 * 10240 (B lo fp8, 128x80 bytes)
#define STEP_SMEM 189440

// ---------------- persistent device scratch ----------------
__device__ __half         g_Wh[5][G4][HID];   // hi: W_hh1, W_ih2, W_hh2, W_ih3, W_hh3
__device__ unsigned char  g_Wl8[5][G4][HID];  // lo residual, e4m3 * 2^14, byte-permuted
__device__ __half         g_Mwh[G4][HID];     // Mw = W_ih1 @ W_dec
__device__ unsigned char  g_Mwl8[G4][HID];
__device__ __half         g_W1h[G4][KP];      // W_ih1 padded 132->192
__device__ unsigned char  g_W1l8[G4][KP];
__device__ __half         g_xh[NT][NB][KP];   // frames padded, hi/lo fp16
__device__ __half         g_xl[NT][NB][KP];
__device__ float          g_hf[2][3][NB][HID];
__device__ __half         g_hh[2][3][NB][HID];
__device__ __half         g_hl[2][3][NB][HID];
__device__ float          g_c[3][NB][HID];
__device__ float          g_bs[3][G4];        // b_ih + b_hh
__device__ float          g_bsM[G4];          // g_bs[0] + W_ih1@b_dec
__device__ unsigned       g_bar;              // grid barrier (monotonic)

// byte permutation within each 16-byte k-group so a fragment is one LDS.u32:
// pair q=(i&7)>>1 -> word q, hi8 flag -> upper half
__host__ __device__ __forceinline__ int perm8(int k) {
    int g = k >> 4, i = k & 15;
    return (g << 4) | (((i & 7) >> 1) << 2) | (((i >> 3) & 1) << 1) | (i & 1);
}

// ---------------- asm helpers ----------------
__device__ __forceinline__ unsigned sptr(const void* p) {
    return (unsigned)__cvta_generic_to_shared(p);
}
__device__ __forceinline__ void cpa16(void* s, const void* g) {
    asm volatile("cp.async.cg.shared.global [%0], [%1], 16;" :: "r"(sptr(s)), "l"(g));
}
__device__ __forceinline__ void cpcommit() { asm volatile("cp.async.commit_group;"); }
__device__ __forceinline__ void cpwait3()  { asm volatile("cp.async.wait_group 3;"); }

__device__ __forceinline__ void ldmA4(unsigned a[4], unsigned addr) {
    asm volatile("ldmatrix.sync.aligned.m8n8.x4.shared.b16 {%0,%1,%2,%3}, [%4];"
                 : "=r"(a[0]), "=r"(a[1]), "=r"(a[2]), "=r"(a[3]) : "r"(addr));
}
__device__ __forceinline__ void ldmB2(unsigned b[2], unsigned addr) {
    asm volatile("ldmatrix.sync.aligned.m8n8.x2.shared.b16 {%0,%1}, [%2];"
                 : "=r"(b[0]), "=r"(b[1]) : "r"(addr));
}
__device__ __forceinline__ void mma16816(float c[4], const unsigned a[4], const unsigned b[2]) {
    asm volatile("mma.sync.aligned.m16n8k16.row.col.f32.f16.f16.f32 "
                 "{%0,%1,%2,%3}, {%4,%5,%6,%7}, {%8,%9}, {%0,%1,%2,%3};"
                 : "+f"(c[0]), "+f"(c[1]), "+f"(c[2]), "+f"(c[3])
                 : "r"(a[0]), "r"(a[1]), "r"(a[2]), "r"(a[3]), "r"(b[0]), "r"(b[1]));
}
__device__ __forceinline__ unsigned cvt8x2(unsigned short v) {
    unsigned r;
    asm("cvt.rn.f16x2.e4m3x2 %0, %1;" : "=r"(r) : "h"(v));
    return r;
}
__device__ __forceinline__ float sigm(float x) { return 1.0f / (1.0f + __expf(-x)); }
__device__ __forceinline__ int growf(int n, int j0) { return ((n >> 5) << 10) + j0 + (n & 31); }

// ---------------- grid barrier (all NBLK blocks resident) ----------------
__device__ __forceinline__ void gridbar() {
    __syncthreads();
    if (threadIdx.x == 0) {
        __threadfence();
        unsigned gen = atomicAdd(&g_bar, 1u);
        unsigned target = gen - (gen % NBLK) + NBLK;
        while (*(volatile unsigned*)&g_bar < target) { }
        __threadfence();
    }
    __syncthreads();
}

// ---------------- decoder core (512-thread block) ----------------
// smf: sh2[32][257] fp32, then sWd[4][257]
__device__ void dec_core(float* smf, int db, int tid,
                         const float* __restrict__ h2, const float* __restrict__ wdec,
                         const float* __restrict__ bdec, float* __restrict__ outp, int toff)
{
    float* sh2 = smf;
    float* sWd = smf + 32 * 257;
    const int o0 = db * 4;
    const int oo = tid & 3, b = (tid >> 2) & 31;
    float acc = 0.0f;
    for (int k0 = 0; k0 < HID; k0 += 256) {
        __syncthreads();
        for (int li = tid; li < 8192; li += 512) {
            int r = li >> 8, c = li & 255;
            sh2[r * 257 + c] = h2[r * HID + k0 + c];
        }
        for (int li = tid; li < 1024; li += 512) {
            int r = li >> 8, c = li & 255;
            sWd[r * 257 + c] = wdec[(o0 + r) * HID + k0 + c];
        }
        __syncthreads();
        if (tid < 128) {
#pragma unroll 8
            for (int k = 0; k < 256; k++)
                acc += sh2[b * 257 + k] * sWd[oo * 257 + k];
        }
    }
    if (tid < 128)
        outp[b * OUTW + toff + o0 + oo] = acc + bdec[o0 + oo];
}

// ---------------- prep 1 ----------------
__global__ void k_prep1(
    const float* __restrict__ wih1, const float* __restrict__ whh1,
    const float* __restrict__ wih2, const float* __restrict__ whh2,
    const float* __restrict__ wih3, const float* __restrict__ whh3,
    const float* __restrict__ seq,
    const float* __restrict__ bi1, const float* __restrict__ bh1,
    const float* __restrict__ bi2, const float* __restrict__ bh2,
    const float* __restrict__ bi3, const float* __restrict__ bh3)
{
    const long i0 = (long)blockIdx.x * blockDim.x + threadIdx.x;
    const long stride = (long)gridDim.x * blockDim.x;

    // 5 weight matrices -> fp16 hi + permuted fp8 lo
    for (long i = i0; i < 5L * G4 * HID; i += stride) {
        int m = (int)(i >> 22);
        long off = i & 4194303L;
        int r = (int)(off >> 10), k = (int)(off & 1023);
        const float* p = (m == 0) ? whh1 : (m == 1) ? wih2 : (m == 2) ? whh2
                                 : (m == 3) ? wih3 : whh3;
        float v = p[off];
        __half hi = __float2half_rn(v);
        float lo = v - __half2float(hi);
        g_Wh[m][r][k] = hi;
        g_Wl8[m][r][perm8(k)] =
            __nv_cvt_float_to_fp8(lo * LO_SCALE, __NV_SATFINITE, __NV_E4M3);
    }
    // W_ih1 padded 132 -> 192
    for (long i = i0; i < (long)G4 * KP; i += stride) {
        int r = (int)(i / KP), k = (int)(i % KP);
        float v = (k < IND) ? wih1[r * IND + k] : 0.0f;
        __half hi = __float2half_rn(v);
        float lo = v - __half2float(hi);
        g_W1h[r][k] = hi;
        g_W1l8[r][perm8(k)] =
            __nv_cvt_float_to_fp8(lo * LO_SCALE, __NV_SATFINITE, __NV_E4M3);
    }
    // frames: seq[b][t][k] -> g_x[t][b][k] padded, hi/lo fp16
    for (long i = i0; i < (long)NT * NB * KP; i += stride) {
        int t = (int)(i / (NB * KP));
        int rem = (int)(i % (NB * KP));
        int b = rem / KP, k = rem % KP;
        float v = (k < IND) ? seq[((long)b * NT + t) * IND + k] : 0.0f;
        __half hi = __float2half_rn(v);
        (&g_xh[0][0][0])[i] = hi;
        (&g_xl[0][0][0])[i] = __float2half_rn(v - __half2float(hi));
    }
    // bias sums
    for (long i = i0; i < 3L * G4; i += stride) {
        int l = (int)(i >> 12), r = (int)(i & 4095);
        const float* pi = (l == 0) ? bi1 : (l == 1) ? bi2 : bi3;
        const float* ph = (l == 0) ? bh1 : (l == 1) ? bh2 : bh3;
        g_bs[l][r] = pi[r] + ph[r];
    }
    // zero state (fresh every replay -> deterministic)
    for (long i = i0; i < 3L * NB * HID; i += stride) (&g_c[0][0][0])[i] = 0.0f;
    for (long i = i0; i < 2L * 3 * NB * HID; i += stride) {
        (&g_hf[0][0][0][0])[i] = 0.0f;
        (&g_hh[0][0][0][0])[i] = __float2half_rn(0.0f);
        (&g_hl[0][0][0][0])[i] = __float2half_rn(0.0f);
    }
}

// ---------------- prep 2: Mw = W_ih1 @ W_dec + bsM ----------------
__global__ void k_mw(const float* __restrict__ wih1, const float* __restrict__ wdec,
                     const float* __restrict__ bdec)
{
    extern __shared__ __align__(16) char smraw[];
    const int tid = threadIdx.x, bid = blockIdx.x;

    if (bid >= 512) {  // bsM: 16 blocks x 256 threads = 4096 rows
        int r = (bid - 512) * 256 + tid;
        float a = 0.0f;
        for (int j = 0; j < IND; j++) a += wih1[r * IND + j] * bdec[j];
        g_bsM[r] = g_bs[0][r] + a;
        return;
    }
    float* sW1 = (float*)smraw;              // [128][133]
    float* sWd = (float*)smraw + 128 * 133;  // [132][64]
    const int r0 = (bid >> 4) * 128;
    const int c0 = (bid & 15) * 64;

    for (int li = tid; li < 128 * IND; li += 256) {
        int rr = li / IND, jj = li % IND;
        sW1[rr * 133 + jj] = wih1[(r0 + rr) * IND + jj];
    }
    for (int li = tid; li < IND * 64; li += 256) {
        int j = li >> 6, cc = li & 63;
        sWd[j * 64 + cc] = wdec[j * HID + c0 + cc];
    }
    __syncthreads();

    const int ty = tid >> 4, tx = tid & 15;
    float a[8][4];
#pragma unroll
    for (int i = 0; i < 8; i++)
#pragma unroll
        for (int q = 0; q < 4; q++) a[i][q] = 0.0f;

    for (int j = 0; j < IND; j++) {
        float4 wd = *(const float4*)&sWd[j * 64 + tx * 4];
#pragma unroll
        for (int i = 0; i < 8; i++) {
            float w1 = sW1[(ty + 16 * i) * 133 + j];
            a[i][0] += w1 * wd.x; a[i][1] += w1 * wd.y;
            a[i][2] += w1 * wd.z; a[i][3] += w1 * wd.w;
        }
    }
#pragma unroll
    for (int i = 0; i < 8; i++)
#pragma unroll
        for (int q = 0; q < 4; q++) {
            int r = r0 + ty + 16 * i, c = c0 + tx * 4 + q;
            float v = a[i][q];
            __half hi = __float2half_rn(v);
            float lo = v - __half2float(hi);
            g_Mwh[r][c] = hi;
            g_Mwl8[r][perm8(c)] =
                __nv_cvt_float_to_fp8(lo * LO_SCALE, __NV_SATFINITE, __NV_E4M3);
        }
}

// ---------------- persistent kernel: all 100 steps ----------------
// blocks 0..95: gate tiles (layer = bid/32, 32 hidden units x 4 gates)
// blocks 96..128: decoder for step t-1 (concurrent), + tail decode of step 99
__global__ void __launch_bounds__(512, 1)
k_all(const float* __restrict__ wdec, const float* __restrict__ bdec,
      float* __restrict__ dout)
{
    extern __shared__ __align__(16) char smraw[];
    const int tid = threadIdx.x, bid = blockIdx.x;

    if (bid >= 96) {
        const int db = bid - 96;
        for (int t = 0; t < NT; t++) {
            if (t > 0)
                dec_core((float*)smraw, db, tid, &g_hf[(t & 1) ^ 1][2][0][0],
                         wdec, bdec, dout, (t - 1) * IND);
            gridbar();
        }
        dec_core((float*)smraw, db, tid, &g_hf[1][2][0][0], wdec, bdec, dout, 99 * IND);
        return;
    }

    const int l = bid >> 5, j0 = (bid & 31) << 5;
    const int lane = tid & 31, warp = tid >> 5;
    const int grp = warp >> 3, wn = warp & 7;   // k-split group, n-tile warp

    // ---- stage-invariant copy geometry (512 threads share each stage) ----
    const int aT = tid & 255;
    const int aRow = aT >> 3, aKo = (aT & 7) << 3;      // A: 256 chunks per matrix
    const bool isAh = (tid < 256);
    int bRow[2], bKo[2], bG[2];                          // B-hi: 1024 chunks -> 2/thread
#pragma unroll
    for (int i = 0; i < 2; i++) {
        int c = tid + (i << 9);
        bRow[i] = c >> 3; bKo[i] = (c & 7) << 3;
        bG[i] = growf(bRow[i], j0);
    }
    const int b8Row = tid >> 2, b8Ch = (tid & 3) << 4;   // B-fp8: 512 chunks -> 1/thread
    const int b8G = growf(b8Row, j0);

    for (int t = 0; t < NT; t++) {
        const int prev = (t & 1) ^ 1, cur = t & 1;
        const int gt = (t % 10) < 5;

        // segment descriptors
        const __half *Ah[2], *Al[2], *Bh[2];
        const unsigned char* B8s[2];
        int aStr[2], bStr[2], nst1;
        if (l == 0) {
            if (gt) {
                Ah[0] = &g_xh[t][0][0]; Al[0] = &g_xl[t][0][0]; aStr[0] = KP;
                Bh[0] = &g_W1h[0][0];   B8s[0] = &g_W1l8[0][0]; bStr[0] = KP;
                nst1 = 3;
            } else {
                Ah[0] = &g_hh[prev][2][0][0]; Al[0] = &g_hl[prev][2][0][0]; aStr[0] = HID;
                Bh[0] = &g_Mwh[0][0];         B8s[0] = &g_Mwl8[0][0];       bStr[0] = HID;
                nst1 = 16;
            }
            Ah[1] = &g_hh[prev][0][0][0]; Al[1] = &g_hl[prev][0][0][0];
            Bh[1] = &g_Wh[0][0][0];       B8s[1] = &g_Wl8[0][0][0];
        } else if (l == 1) {
            Ah[0] = &g_hh[prev][0][0][0]; Al[0] = &g_hl[prev][0][0][0]; aStr[0] = HID;
            Bh[0] = &g_Wh[1][0][0];       B8s[0] = &g_Wl8[1][0][0];     bStr[0] = HID;
            nst1 = 16;
            Ah[1] = &g_hh[prev][1][0][0]; Al[1] = &g_hl[prev][1][0][0];
            Bh[1] = &g_Wh[2][0][0];       B8s[1] = &g_Wl8[2][0][0];
        } else {
            Ah[0] = &g_hh[prev][1][0][0]; Al[0] = &g_hl[prev][1][0][0]; aStr[0] = HID;
            Bh[0] = &g_Wh[3][0][0];       B8s[0] = &g_Wl8[3][0][0];     bStr[0] = HID;
            nst1 = 16;
            Ah[1] = &g_hh[prev][2][0][0]; Al[1] = &g_hl[prev][2][0][0];
            Bh[1] = &g_Wh[4][0][0];       B8s[1] = &g_Wl8[4][0][0];
        }
        aStr[1] = HID; bStr[1] = HID;
        const int nstTot = nst1 + 16;

        auto issue = [&](int s) {
            const int seg = (s >= nst1) ? 1 : 0;
            const int k0 = (s - (seg ? nst1 : 0)) << 6;
            const int slot = s % DEPTH;
            if (isAh) {
                __half* dA = (__half*)(smraw + SM_AH) + slot * 2304 + aRow * ASTR + aKo;
                cpa16(dA, Ah[seg] + aRow * aStr[seg] + k0 + aKo);
            } else {
                __half* dA = (__half*)(smraw + SM_AL) + slot * 2304 + aRow * ASTR + aKo;
                cpa16(dA, Al[seg] + aRow * aStr[seg] + k0 + aKo);
            }
            __half* dBh = (__half*)(smraw + SM_BH) + slot * 9216;
#pragma unroll
            for (int i = 0; i < 2; i++)
                cpa16(dBh + bRow[i] * ASTR + bKo[i],
                      Bh[seg] + (size_t)bG[i] * bStr[seg] + k0 + bKo[i]);
            unsigned char* dB8 = (unsigned char*)(smraw + SM_B8) + slot * 10240;
            cpa16(dB8 + b8Row * 80 + b8Ch,
                  B8s[seg] + (size_t)b8G * bStr[seg] + k0 + b8Ch);
        };

        float accH[2][2][4], accL[2][2][4];
#pragma unroll
        for (int a = 0; a < 2; a++)
#pragma unroll
            for (int b = 0; b < 2; b++)
#pragma unroll
                for (int c = 0; c < 4; c++) { accH[a][b][c] = 0.0f; accL[a][b][c] = 0.0f; }

#pragma unroll
        for (int s = 0; s < DEPTH - 1; s++) { issue(s); cpcommit(); }

        for (int s = 0; s < nstTot; s++) {
            cpwait3();
            __syncthreads();
            const int slot = s % DEPTH;
            const __half* Abh = (const __half*)(smraw + SM_AH) + slot * 2304;
            const __half* Abl = (const __half*)(smraw + SM_AL) + slot * 2304;
            const __half* Bbh = (const __half*)(smraw + SM_BH) + slot * 9216;
            const unsigned char* Bb8 = (const unsigned char*)(smraw + SM_B8) + slot * 10240;

#pragma unroll
            for (int ki = 0; ki < 2; ki++) {
                const int kk = (grp << 5) + (ki << 4);   // this group's k-half
                unsigned ah0[4], ah1[4], al0[4], al1[4];
                const int aoff = (lane & 15) * ASTR + kk + ((lane >> 4) << 3);
                ldmA4(ah0, sptr(Abh + aoff));
                ldmA4(ah1, sptr(Abh + 16 * ASTR + aoff));
                ldmA4(al0, sptr(Abl + aoff));
                ldmA4(al1, sptr(Abl + 16 * ASTR + aoff));
#pragma unroll
                for (int nf = 0; nf < 2; nf++) {
                    unsigned bh[2], bl[2];
                    const int boff = ((wn << 4) + (nf << 3) + (lane & 7)) * ASTR +
                                     kk + (((lane >> 3) & 1) << 3);
                    ldmB2(bh, sptr(Bbh + boff));
                    unsigned u = *(const unsigned*)(Bb8 +
                                  ((wn << 4) + (nf << 3) + (lane >> 2)) * 80 +
                                  kk + ((lane & 3) << 2));
                    bl[0] = cvt8x2((unsigned short)(u & 0xffffu));
                    bl[1] = cvt8x2((unsigned short)(u >> 16));
                    mma16816(accH[0][nf], ah0, bh);
                    mma16816(accH[1][nf], ah1, bh);
                    mma16816(accH[0][nf], al0, bh);
                    mma16816(accH[1][nf], al1, bh);
                    mma16816(accL[0][nf], ah0, bl);
                    mma16816(accL[1][nf], ah1, bl);
                }
            }
            if (s + DEPTH - 1 < nstTot) issue(s + DEPTH - 1);
            cpcommit();   // unconditional: wait_group 3 stays uniformly correct
        }
        __syncthreads();

        // ---- epilogue: both k-groups stage partial gates in smem ----
        float* G = (float*)smraw;   // [2][32][132]
#pragma unroll
        for (int mi = 0; mi < 2; mi++)
#pragma unroll
            for (int nf = 0; nf < 2; nf++)
#pragma unroll
                for (int r = 0; r < 4; r++) {
                    int m = mi * 16 + (lane >> 2) + ((r >> 1) << 3);
                    int n = (wn << 4) + (nf << 3) + ((lane & 3) << 1) + (r & 1);
                    float v = accH[mi][nf][r] + accL[mi][nf][r] * LO_INV;
                    if (grp == 0) {
                        int row = growf(n, j0);
                        v += (l == 0 && !gt) ? g_bsM[row] : g_bs[l][row];
                    }
                    G[grp * 4224 + m * 132 + n] = v;
                }
        __syncthreads();

        // ---- pointwise LSTM update (512 threads, 2 units each) ----
        const int b = tid >> 4;
        const int jj0 = (tid & 15) << 1;
#pragma unroll
        for (int q = 0; q < 2; q++) {
            const int jj = jj0 + q, j = j0 + jj;
            float gi = G[b * 132 + jj]      + G[4224 + b * 132 + jj];
            float gf = G[b * 132 + 32 + jj] + G[4224 + b * 132 + 32 + jj];
            float gg = G[b * 132 + 64 + jj] + G[4224 + b * 132 + 64 + jj];
            float go = G[b * 132 + 96 + jj] + G[4224 + b * 132 + 96 + jj];
            float c0 = g_c[l][b][j];
            float cn = sigm(gf) * c0 + sigm(gi) * tanhf(gg);
            float hn = sigm(go) * tanhf(cn);
            g_c[l][b][j] = cn;
            g_hf[cur][l][b][j] = hn;
            __half hh2 = __float2half_rn(hn);
            g_hh[cur][l][b][j] = hh2;
            g_hl[cur][l][b][j] = __float2half_rn(hn - __half2float(hh2));
        }

        gridbar();
    }
}

// ---------------- host ----------------
#define MW_SMEM 101888  // (128*133 + 132*64) * 4

extern "C" void kernel_launch(void* const* d_in, const int* in_sizes, int n_in,
                              void* d_out, int out_size) {
    (void)in_sizes; (void)n_in; (void)out_size;
    const float* seq  = (const float*)d_in[0];
    const float* Wih1 = (const float*)d_in[1];
    const float* Whh1 = (const float*)d_in[2];
    const float* bih1 = (const float*)d_in[3];
    const float* bhh1 = (const float*)d_in[4];
    const float* Wih2 = (const float*)d_in[5];
    const float* Whh2 = (const float*)d_in[6];
    const float* bih2 = (const float*)d_in[7];
    const float* bhh2 = (const float*)d_in[8];
    const float* Wih3 = (const float*)d_in[9];
    const float* Whh3 = (const float*)d_in[10];
    const float* bih3 = (const float*)d_in[11];
    const float* bhh3 = (const float*)d_in[12];
    const float* Wdec = (const float*)d_in[13];
    const float* bdec = (const float*)d_in[14];
    float* out = (float*)d_out;

    cudaFuncSetAttribute(k_all, cudaFuncAttributeMaxDynamicSharedMemorySize, STEP_SMEM);
    cudaFuncSetAttribute(k_mw, cudaFuncAttributeMaxDynamicSharedMemorySize, MW_SMEM);

    k_prep1<<<2048, 256>>>(Wih1, Whh1, Wih2, Whh2, Wih3, Whh3, seq,
                           bih1, bhh1, bih2, bhh2, bih3, bhh3);
    k_mw<<<528, 256, MW_SMEM>>>(Wih1, Wdec, bdec);
    k_all<<<NBLK, 512, STEP_SMEM>>>(Wdec, bdec, out);
}

// round 10
// speedup vs baseline: 1.3847x; 1.3847x over previous
#include <cuda_runtime.h>
#include <cuda_fp16.h>
#include <cuda_fp8.h>
#include <math.h>

#define HID   1024
#define G4    4096
#define NB    32
#define NT    100
#define IND   132
#define OUTW  13200
#define NBLK  129
#define LO_SCALE 16384.0f
#define LO_I     (1.0f/16384.0f)

// stage tile sizes (bytes)
#define TILE_WH 18432   // 128 rows x 72 halves fp16
#define TILE_W8 10240   // 128 rows x 80 bytes fp8
#define TILE_A  4608    // 32 rows x 72 halves fp16
#define SLOT    37888
#define OF_WH   0
#define OF_W8   18432
#define OF_AH   28672
#define OF_AL   33280
#define CTRL    151552  // 4*SLOT
#define SMEM_ALL 151680
#define TXB     37888

// ---------------- persistent device scratch (pre-tiled) ----------------
// weight tiles: [matrix][jb][kb][row 128][72]  row = gate*32 + r, col = kb*64 + c
// matrices: 0 Whh1, 1 Wih2, 2 Whh2, 3 Wih3, 4 Whh3, 5 Mw(=Wih1@Wdec)
__device__ __half         g_WT[6][32][16][128][72];
__device__ unsigned char  g_W8T[6][32][16][128][80];   // fp8 e4m3 lo * 2^14, perm8 layout
__device__ __half         g_W1T[32][3][128][72];       // Wih1 padded to K=192
__device__ unsigned char  g_W18T[32][3][128][80];
__device__ __half         g_xhT[NT][3][32][72];        // frames, tiled
__device__ __half         g_xlT[NT][3][32][72];
__device__ __half         g_hhT[2][3][16][32][72];     // h hi, tiled per kb
__device__ __half         g_hlT[2][3][16][32][72];     // h lo
__device__ float          g_hf[2][3][NB][HID];         // fp32 h for decoder
__device__ float          g_c[3][NB][HID];
__device__ float          g_bs[3][G4];
__device__ float          g_bsM[G4];
__device__ unsigned       g_bar;

// perm within 16-byte group so a thread's fp8 fragment is one LDS.u32
__device__ __forceinline__ int perm8(int k) {
    int g = k >> 4, i = k & 15;
    return (g << 4) | (((i & 7) >> 1) << 2) | (((i >> 3) & 1) << 1) | (i & 1);
}

// ---------------- asm helpers ----------------
__device__ __forceinline__ unsigned sptr(const void* p) {
    return (unsigned)__cvta_generic_to_shared(p);
}
__device__ __forceinline__ void bulkcp(unsigned dst, const void* src, unsigned bytes,
                                       unsigned mbar) {
    asm volatile(
        "cp.async.bulk.shared::cluster.global.mbarrier::complete_tx::bytes "
        "[%0], [%1], %2, [%3];"
        :: "r"(dst), "l"(src), "r"(bytes), "r"(mbar) : "memory");
}
__device__ __forceinline__ void mbar_init(unsigned a, unsigned cnt) {
    asm volatile("mbarrier.init.shared.b64 [%0], %1;" :: "r"(a), "r"(cnt) : "memory");
}
__device__ __forceinline__ void mbar_expect(unsigned a, unsigned tx) {
    asm volatile("mbarrier.arrive.expect_tx.shared.b64 _, [%0], %1;"
                 :: "r"(a), "r"(tx) : "memory");
}
__device__ __forceinline__ void mbar_arrive(unsigned a) {
    asm volatile("mbarrier.arrive.shared.b64 _, [%0];" :: "r"(a) : "memory");
}
__device__ __forceinline__ void mbar_wait(unsigned a, unsigned par) {
    asm volatile(
        "{\n\t.reg .pred P;\n\t"
        "W_%=:\n\t"
        "mbarrier.try_wait.parity.acquire.cta.shared::cta.b64 P, [%0], %1, 0x989680;\n\t"
        "@P bra.uni D_%=;\n\t"
        "bra.uni W_%=;\n\t"
        "D_%=:\n\t}"
        :: "r"(a), "r"(par) : "memory");
}
__device__ __forceinline__ void fence_async() {
    asm volatile("fence.proxy.async.shared::cta;" ::: "memory");
}
__device__ __forceinline__ void ldmA4(unsigned a[4], unsigned addr) {
    asm volatile("ldmatrix.sync.aligned.m8n8.x4.shared.b16 {%0,%1,%2,%3}, [%4];"
                 : "=r"(a[0]), "=r"(a[1]), "=r"(a[2]), "=r"(a[3]) : "r"(addr));
}
__device__ __forceinline__ void ldmB2(unsigned b[2], unsigned addr) {
    asm volatile("ldmatrix.sync.aligned.m8n8.x2.shared.b16 {%0,%1}, [%2];"
                 : "=r"(b[0]), "=r"(b[1]) : "r"(addr));
}
__device__ __forceinline__ void mma16816(float c[4], const unsigned a[4], const unsigned b[2]) {
    asm volatile("mma.sync.aligned.m16n8k16.row.col.f32.f16.f16.f32 "
                 "{%0,%1,%2,%3}, {%4,%5,%6,%7}, {%8,%9}, {%0,%1,%2,%3};"
                 : "+f"(c[0]), "+f"(c[1]), "+f"(c[2]), "+f"(c[3])
                 : "r"(a[0]), "r"(a[1]), "r"(a[2]), "r"(a[3]), "r"(b[0]), "r"(b[1]));
}
__device__ __forceinline__ unsigned cvt8x2(unsigned short v) {
    unsigned r;
    asm("cvt.rn.f16x2.e4m3x2 %0, %1;" : "=r"(r) : "h"(v));
    return r;
}
__device__ __forceinline__ float sigm(float x) { return 1.0f / (1.0f + __expf(-x)); }
__device__ __forceinline__ int growf(int n, int j0) { return ((n >> 5) << 10) + j0 + (n & 31); }

// ---------------- grid barrier ----------------
__device__ __forceinline__ void gridbar() {
    __syncthreads();
    if (threadIdx.x == 0) {
        __threadfence();
        unsigned gen = atomicAdd(&g_bar, 1u);
        unsigned target = gen - (gen % NBLK) + NBLK;
        while (*(volatile unsigned*)&g_bar < target) { }
        __threadfence();
    }
    __syncthreads();
}

// ---------------- decoder core (256-thread block) ----------------
__device__ void dec_core(float* smf, int db, int tid,
                         const float* __restrict__ h2, const float* __restrict__ wdec,
                         const float* __restrict__ bdec, float* __restrict__ outp, int toff)
{
    float* sh2 = smf;
    float* sWd = smf + 32 * 257;
    const int o0 = db * 4;
    const int oo = tid & 3, b = (tid >> 2) & 31;
    float acc = 0.0f;
    for (int k0 = 0; k0 < HID; k0 += 256) {
        __syncthreads();
        for (int li = tid; li < 8192; li += 256) {
            int r = li >> 8, c = li & 255;
            sh2[r * 257 + c] = h2[r * HID + k0 + c];
        }
        for (int li = tid; li < 1024; li += 256) {
            int r = li >> 8, c = li & 255;
            sWd[r * 257 + c] = wdec[(o0 + r) * HID + k0 + c];
        }
        __syncthreads();
        if (tid < 128) {
#pragma unroll 8
            for (int k = 0; k < 256; k++)
                acc += sh2[b * 257 + k] * sWd[oo * 257 + k];
        }
    }
    if (tid < 128)
        outp[b * OUTW + toff + o0 + oo] = acc + bdec[o0 + oo];
}

// ---------------- prep 1: build all tiled operands ----------------
__global__ void k_prep1(
    const float* __restrict__ wih1, const float* __restrict__ whh1,
    const float* __restrict__ wih2, const float* __restrict__ whh2,
    const float* __restrict__ wih3, const float* __restrict__ whh3,
    const float* __restrict__ seq,
    const float* __restrict__ bi1, const float* __restrict__ bh1,
    const float* __restrict__ bi2, const float* __restrict__ bh2,
    const float* __restrict__ bi3, const float* __restrict__ bh3)
{
    const long i0 = (long)blockIdx.x * blockDim.x + threadIdx.x;
    const long stride = (long)gridDim.x * blockDim.x;

    // A) weight tiles m=0..4 data + all fp16 pads (m=0..5)
    for (long i = i0; i < 6L * 32 * 16 * 128 * 72; i += stride) {
        int cc = (int)(i % 72); long t1 = i / 72;
        int tr = (int)(t1 % 128); long t2 = t1 / 128;
        int kb = (int)(t2 % 16); long t3 = t2 / 16;
        int jbb = (int)(t3 % 32);
        int m = (int)(t3 / 32);
        if (cc >= 64) { g_WT[m][jbb][kb][tr][cc] = __float2half_rn(0.0f); continue; }
        if (m == 5) continue;   // Mw data filled by k_mw
        const float* p = (m == 0) ? whh1 : (m == 1) ? wih2 : (m == 2) ? whh2
                                 : (m == 3) ? wih3 : whh3;
        int row = ((tr >> 5) << 10) + jbb * 32 + (tr & 31);
        int k = kb * 64 + cc;
        float v = p[(long)row * HID + k];
        __half hi = __float2half_rn(v);
        g_WT[m][jbb][kb][tr][cc] = hi;
        unsigned char* w8 = &g_W8T[m][jbb][kb][0][0];
        w8[tr * 80 + perm8(cc)] =
            __nv_cvt_float_to_fp8((v - __half2float(hi)) * LO_SCALE,
                                  __NV_SATFINITE, __NV_E4M3);
    }
    // B) fp8 row pads (bytes 64..79)
    for (long i = i0; i < 6L * 32 * 16 * 128 * 16; i += stride) {
        int pb = (int)(i % 16); long t1 = i / 16;
        int tr = (int)(t1 % 128); long t2 = t1 / 128;
        int kb = (int)(t2 % 16); long t3 = t2 / 16;
        int jbb = (int)(t3 % 32); int m = (int)(t3 / 32);
        unsigned char* w8 = &g_W8T[m][jbb][kb][0][0];
        w8[tr * 80 + 64 + pb] = 0;
    }
    // C) W1 tiles (K padded 132->192)
    for (long i = i0; i < 32L * 3 * 128 * 72; i += stride) {
        int cc = (int)(i % 72); long t1 = i / 72;
        int tr = (int)(t1 % 128); long t2 = t1 / 128;
        int kb = (int)(t2 % 3); int jbb = (int)(t2 / 3);
        if (cc >= 64) { g_W1T[jbb][kb][tr][cc] = __float2half_rn(0.0f); continue; }
        int row = ((tr >> 5) << 10) + jbb * 32 + (tr & 31);
        int k = kb * 64 + cc;
        float v = (k < IND) ? wih1[(long)row * IND + k] : 0.0f;
        __half hi = __float2half_rn(v);
        g_W1T[jbb][kb][tr][cc] = hi;
        unsigned char* w8 = &g_W18T[jbb][kb][0][0];
        w8[tr * 80 + perm8(cc)] =
            __nv_cvt_float_to_fp8((v - __half2float(hi)) * LO_SCALE,
                                  __NV_SATFINITE, __NV_E4M3);
    }
    for (long i = i0; i < 32L * 3 * 128 * 16; i += stride) {
        int pb = (int)(i % 16); long t1 = i / 16;
        int tr = (int)(t1 % 128); long t2 = t1 / 128;
        int kb = (int)(t2 % 3); int jbb = (int)(t2 / 3);
        unsigned char* w8 = &g_W18T[jbb][kb][0][0];
        w8[tr * 80 + 64 + pb] = 0;
    }
    // D) frames tiled
    for (long i = i0; i < (long)NT * 3 * 32 * 72; i += stride) {
        int cc = (int)(i % 72); long t1 = i / 72;
        int b = (int)(t1 % 32); long t2 = t1 / 32;
        int kb = (int)(t2 % 3); int t = (int)(t2 / 3);
        float v = 0.0f;
        if (cc < 64) {
            int k = kb * 64 + cc;
            if (k < IND) v = seq[((long)b * NT + t) * IND + k];
        }
        __half hi = __float2half_rn(v);
        g_xhT[t][kb][b][cc] = hi;
        g_xlT[t][kb][b][cc] = __float2half_rn(v - __half2float(hi));
    }
    // E) biases
    for (long i = i0; i < 3L * G4; i += stride) {
        int l = (int)(i >> 12), r = (int)(i & 4095);
        const float* pi = (l == 0) ? bi1 : (l == 1) ? bi2 : bi3;
        const float* ph = (l == 0) ? bh1 : (l == 1) ? bh2 : bh3;
        g_bs[l][r] = pi[r] + ph[r];
    }
    // F) zero state
    for (long i = i0; i < 3L * NB * HID; i += stride) (&g_c[0][0][0])[i] = 0.0f;
    for (long i = i0; i < 2L * 3 * NB * HID; i += stride) (&g_hf[0][0][0][0])[i] = 0.0f;
    for (long i = i0; i < 2L * 3 * 16 * 32 * 72; i += stride) {
        (&g_hhT[0][0][0][0][0])[i] = __float2half_rn(0.0f);
        (&g_hlT[0][0][0][0][0])[i] = __float2half_rn(0.0f);
    }
}

// ---------------- prep 2: Mw = W_ih1 @ W_dec (tiled out) + bsM ----------------
__global__ void k_mw(const float* __restrict__ wih1, const float* __restrict__ wdec,
                     const float* __restrict__ bdec)
{
    extern __shared__ __align__(16) char smraw[];
    const int tid = threadIdx.x, bid = blockIdx.x;

    if (bid >= 512) {
        int r = (bid - 512) * 256 + tid;
        float a = 0.0f;
        for (int j = 0; j < IND; j++) a += wih1[r * IND + j] * bdec[j];
        g_bsM[r] = g_bs[0][r] + a;
        return;
    }
    float* sW1 = (float*)smraw;              // [128][133]
    float* sWd = (float*)smraw + 128 * 133;  // [132][64]
    const int r0 = (bid >> 4) * 128;
    const int c0 = (bid & 15) * 64;

    for (int li = tid; li < 128 * IND; li += 256) {
        int rr = li / IND, jj = li % IND;
        sW1[rr * 133 + jj] = wih1[(r0 + rr) * IND + jj];
    }
    for (int li = tid; li < IND * 64; li += 256) {
        int j = li >> 6, cc = li & 63;
        sWd[j * 64 + cc] = wdec[j * HID + c0 + cc];
    }
    __syncthreads();

    const int ty = tid >> 4, tx = tid & 15;
    float a[8][4];
#pragma unroll
    for (int i = 0; i < 8; i++)
#pragma unroll
        for (int q = 0; q < 4; q++) a[i][q] = 0.0f;

    for (int j = 0; j < IND; j++) {
        float4 wd = *(const float4*)&sWd[j * 64 + tx * 4];
#pragma unroll
        for (int i = 0; i < 8; i++) {
            float w1 = sW1[(ty + 16 * i) * 133 + j];
            a[i][0] += w1 * wd.x; a[i][1] += w1 * wd.y;
            a[i][2] += w1 * wd.z; a[i][3] += w1 * wd.w;
        }
    }
#pragma unroll
    for (int i = 0; i < 8; i++)
#pragma unroll
        for (int q = 0; q < 4; q++) {
            int r = r0 + ty + 16 * i, c = c0 + tx * 4 + q;
            float v = a[i][q];
            __half hi = __float2half_rn(v);
            int gate = r >> 10, win = r & 1023;
            int jbb = win >> 5, tr = gate * 32 + (win & 31);
            int kb = c >> 6, cc = c & 63;
            g_WT[5][jbb][kb][tr][cc] = hi;
            unsigned char* w8 = &g_W8T[5][jbb][kb][0][0];
            w8[tr * 80 + perm8(cc)] =
                __nv_cvt_float_to_fp8((v - __half2float(hi)) * LO_SCALE,
                                      __NV_SATFINITE, __NV_E4M3);
        }
}

// ---------------- persistent kernel: all 100 steps ----------------
__global__ void __launch_bounds__(256, 1)
k_all(const float* __restrict__ wdec, const float* __restrict__ bdec,
      float* __restrict__ dout)
{
    extern __shared__ __align__(16) char smraw[];
    const int tid = threadIdx.x, bid = blockIdx.x;

    if (bid >= 96) {   // ---- decoder blocks ----
        const int db = bid - 96;
        for (int t = 0; t < NT; t++) {
            if (t > 0)
                dec_core((float*)smraw, db, tid, &g_hf[(t & 1) ^ 1][2][0][0],
                         wdec, bdec, dout, (t - 1) * IND);
            gridbar();
        }
        dec_core((float*)smraw, db, tid, &g_hf[1][2][0][0], wdec, bdec, dout, 99 * IND);
        return;
    }

    // ---- gate blocks ----
    const int l = bid >> 5, jb = bid & 31, j0 = jb << 5;
    const int lane = tid & 31, w = tid >> 5;
    const unsigned smb = sptr(smraw);
    const unsigned fullB = smb + CTRL;        // 4 x 8B
    const unsigned emptyB = smb + CTRL + 32;  // 4 x 8B

    if (tid == 0) {
        for (int s = 0; s < 4; s++) { mbar_init(fullB + s * 8, 1); mbar_init(emptyB + s * 8, 8); }
    }
    fence_async();
    __syncthreads();

    int sg = 0;
    for (int t = 0; t < NT; t++) {
        const int prev = (t & 1) ^ 1, cur = t & 1;
        const int gt = (t % 10) < 5;

        const char *Wt0, *Wt1, *W8t0, *W8t1, *Aht0, *Aht1, *Alt0, *Alt1;
        int nst1;
        if (l == 0) {
            if (gt) {
                Wt0 = (const char*)&g_W1T[jb][0][0][0];  W8t0 = (const char*)&g_W18T[jb][0][0][0];
                Aht0 = (const char*)&g_xhT[t][0][0][0];  Alt0 = (const char*)&g_xlT[t][0][0][0];
                nst1 = 3;
            } else {
                Wt0 = (const char*)&g_WT[5][jb][0][0][0];
                W8t0 = (const char*)&g_W8T[5][jb][0][0][0];
                Aht0 = (const char*)&g_hhT[prev][2][0][0][0];
                Alt0 = (const char*)&g_hlT[prev][2][0][0][0];
                nst1 = 16;
            }
            Wt1 = (const char*)&g_WT[0][jb][0][0][0]; W8t1 = (const char*)&g_W8T[0][jb][0][0][0];
            Aht1 = (const char*)&g_hhT[prev][0][0][0][0];
            Alt1 = (const char*)&g_hlT[prev][0][0][0][0];
        } else if (l == 1) {
            Wt0 = (const char*)&g_WT[1][jb][0][0][0]; W8t0 = (const char*)&g_W8T[1][jb][0][0][0];
            Aht0 = (const char*)&g_hhT[prev][0][0][0][0];
            Alt0 = (const char*)&g_hlT[prev][0][0][0][0];
            Wt1 = (const char*)&g_WT[2][jb][0][0][0]; W8t1 = (const char*)&g_W8T[2][jb][0][0][0];
            Aht1 = (const char*)&g_hhT[prev][1][0][0][0];
            Alt1 = (const char*)&g_hlT[prev][1][0][0][0];
            nst1 = 16;
        } else {
            Wt0 = (const char*)&g_WT[3][jb][0][0][0]; W8t0 = (const char*)&g_W8T[3][jb][0][0][0];
            Aht0 = (const char*)&g_hhT[prev][1][0][0][0];
            Alt0 = (const char*)&g_hlT[prev][1][0][0][0];
            Wt1 = (const char*)&g_WT[4][jb][0][0][0]; W8t1 = (const char*)&g_W8T[4][jb][0][0][0];
            Aht1 = (const char*)&g_hhT[prev][2][0][0][0];
            Alt1 = (const char*)&g_hlT[prev][2][0][0][0];
            nst1 = 16;
        }
        const int nst = nst1 + 16;

        auto refill = [&](int g) {
            const int slot = g & 3, u = g >> 2;
            if (u > 0) mbar_wait(emptyB + slot * 8, (u - 1) & 1);
            const int ls = g - sg;
            const int seg = (ls >= nst1);
            const int kb = seg ? (ls - nst1) : ls;
            const unsigned d = smb + slot * SLOT;
            const unsigned fb = fullB + slot * 8;
            mbar_expect(fb, TXB);
            bulkcp(d + OF_WH, (seg ? Wt1 : Wt0) + (long)kb * TILE_WH, TILE_WH, fb);
            bulkcp(d + OF_W8, (seg ? W8t1 : W8t0) + (long)kb * TILE_W8, TILE_W8, fb);
            bulkcp(d + OF_AH, (seg ? Aht1 : Aht0) + (long)kb * TILE_A, TILE_A, fb);
            bulkcp(d + OF_AL, (seg ? Alt1 : Alt0) + (long)kb * TILE_A, TILE_A, fb);
        };

        float accH[2][2][4], accL[2][2][4];
#pragma unroll
        for (int a = 0; a < 2; a++)
#pragma unroll
            for (int b = 0; b < 2; b++)
#pragma unroll
                for (int c = 0; c < 4; c++) { accH[a][b][c] = 0.0f; accL[a][b][c] = 0.0f; }

        if (tid == 0) { refill(sg); refill(sg + 1); refill(sg + 2); }

        for (int s = 0; s < nst; s++) {
            const int g = sg + s, slot = g & 3;
            if (tid == 0 && s + 3 < nst) refill(g + 3);
            mbar_wait(fullB + slot * 8, (g >> 2) & 1);

            const char* sb = smraw + slot * SLOT;
            const __half* Abh = (const __half*)(sb + OF_AH);
            const __half* Abl = (const __half*)(sb + OF_AL);
            const __half* Bbh = (const __half*)(sb + OF_WH);
            const unsigned char* Bb8 = (const unsigned char*)(sb + OF_W8);

#pragma unroll
            for (int kk = 0; kk < 64; kk += 16) {
                unsigned ah0[4], ah1[4], al0[4], al1[4];
                const int aoff = (lane & 15) * 72 + kk + ((lane >> 4) << 3);
                ldmA4(ah0, sptr(Abh + aoff));
                ldmA4(ah1, sptr(Abh + 16 * 72 + aoff));
                ldmA4(al0, sptr(Abl + aoff));
                ldmA4(al1, sptr(Abl + 16 * 72 + aoff));
#pragma unroll
                for (int nf = 0; nf < 2; nf++) {
                    unsigned bh[2], bl[2];
                    const int boff = ((w << 4) + (nf << 3) + (lane & 7)) * 72 +
                                     kk + (((lane >> 3) & 1) << 3);
                    ldmB2(bh, sptr(Bbh + boff));
                    unsigned u = *(const unsigned*)(Bb8 +
                                  ((w << 4) + (nf << 3) + (lane >> 2)) * 80 +
                                  kk + ((lane & 3) << 2));
                    bl[0] = cvt8x2((unsigned short)(u & 0xffffu));
                    bl[1] = cvt8x2((unsigned short)(u >> 16));
                    mma16816(accH[0][nf], ah0, bh);
                    mma16816(accH[1][nf], ah1, bh);
                    mma16816(accH[0][nf], al0, bh);
                    mma16816(accH[1][nf], al1, bh);
                    mma16816(accL[0][nf], ah0, bl);
                    mma16816(accL[1][nf], ah1, bl);
                }
            }
            if (lane == 0) mbar_arrive(emptyB + slot * 8);
        }
        __syncthreads();   // all warps done with smem before G staging

        // ---- epilogue: gates -> smem -> pointwise ----
        float* G = (float*)smraw;   // [32][129] fp32, fits in slot0 Wh area
#pragma unroll
        for (int mi = 0; mi < 2; mi++)
#pragma unroll
            for (int nf = 0; nf < 2; nf++)
#pragma unroll
                for (int r = 0; r < 4; r++) {
                    int m = mi * 16 + (lane >> 2) + ((r >> 1) << 3);
                    int n = (w << 4) + (nf << 3) + ((lane & 3) << 1) + (r & 1);
                    int row = growf(n, j0);
                    float bias = (l == 0 && !gt) ? g_bsM[row] : g_bs[l][row];
                    G[m * 129 + n] = accH[mi][nf][r] + accL[mi][nf][r] * LO_I + bias;
                }
        __syncthreads();

        {
            const int b = tid >> 3;
            const int jj0 = (tid & 7) << 2;
#pragma unroll
            for (int q = 0; q < 4; q++) {
                const int jj = jj0 + q, j = j0 + jj;
                float gi = G[b * 129 + jj];
                float gf = G[b * 129 + 32 + jj];
                float gg = G[b * 129 + 64 + jj];
                float go = G[b * 129 + 96 + jj];
                float c0 = g_c[l][b][j];
                float cn = sigm(gf) * c0 + sigm(gi) * tanhf(gg);
                float hn = sigm(go) * tanhf(cn);
                g_c[l][b][j] = cn;
                g_hf[cur][l][b][j] = hn;
                __half hh2 = __float2half_rn(hn);
                const int kb = j >> 6, cc = j & 63;
                g_hhT[cur][l][kb][b][cc] = hh2;
                g_hlT[cur][l][kb][b][cc] = __float2half_rn(hn - __half2float(hh2));
            }
        }
        sg += nst;
        gridbar();
    }
}

// ---------------- host ----------------
#define MW_SMEM 101888

extern "C" void kernel_launch(void* const* d_in, const int* in_sizes, int n_in,
                              void* d_out, int out_size) {
    (void)in_sizes; (void)n_in; (void)out_size;
    const float* seq  = (const float*)d_in[0];
    const float* Wih1 = (const float*)d_in[1];
    const float* Whh1 = (const float*)d_in[2];
    const float* bih1 = (const float*)d_in[3];
    const float* bhh1 = (const float*)d_in[4];
    const float* Wih2 = (const float*)d_in[5];
    const float* Whh2 = (const float*)d_in[6];
    const float* bih2 = (const float*)d_in[7];
    const float* bhh2 = (const float*)d_in[8];
    const float* Wih3 = (const float*)d_in[9];
    const float* Whh3 = (const float*)d_in[10];
    const float* bih3 = (const float*)d_in[11];
    const float* bhh3 = (const float*)d_in[12];
    const float* Wdec = (const float*)d_in[13];
    const float* bdec = (const float*)d_in[14];
    float* out = (float*)d_out;

    cudaFuncSetAttribute(k_all, cudaFuncAttributeMaxDynamicSharedMemorySize, SMEM_ALL);
    cudaFuncSetAttribute(k_mw, cudaFuncAttributeMaxDynamicSharedMemorySize, MW_SMEM);

    k_prep1<<<2048, 256>>>(Wih1, Whh1, Wih2, Whh2, Wih3, Whh3, seq,
                           bih1, bhh1, bih2, bhh2, bih3, bhh3);
    k_mw<<<528, 256, MW_SMEM>>>(Wih1, Wdec, bdec);
    k_all<<<NBLK, 256, SMEM_ALL>>>(Wdec, bdec, out);
}

// round 11
// speedup vs baseline: 1.4372x; 1.0379x over previous
#include <cuda_runtime.h>
#include <cuda_fp16.h>
#include <cuda_fp8.h>
#include <math.h>

#define HID   1024
#define G4    4096
#define NB    32
#define NT    100
#define IND   132
#define OUTW  13200
#define NBLK  129
#define LO_SCALE 16384.0f
#define LO_I     (1.0f/16384.0f)

// stage tile sizes (bytes)
#define TILE_WH 18432   // 128 rows x 72 halves fp16
#define TILE_W8 10240   // 128 rows x 80 bytes fp8
#define TILE_A  4608    // 32 rows x 72 halves fp16
#define SLOT    33280
#define OF_WH   0
#define OF_W8   18432
#define OF_AH   28672
#define CTRL    133120  // 4*SLOT
#define SMEM_ALL 133248
#define TXB     33280

// ---------------- persistent device scratch (pre-tiled) ----------------
// weight tiles: [matrix][jb][kb][row 128][72]  row = gate*32 + r, col = kb*64 + c
// matrices: 0 Whh1, 1 Wih2, 2 Whh2, 3 Wih3, 4 Whh3, 5 Mw(=Wih1@Wdec)
__device__ __half         g_WT[6][32][16][128][72];
__device__ unsigned char  g_W8T[6][32][16][128][80];   // fp8 e4m3 lo * 2^14, perm8 layout
__device__ __half         g_W1T[32][3][128][72];       // Wih1 padded to K=192
__device__ unsigned char  g_W18T[32][3][128][80];
__device__ __half         g_xhT[NT][3][32][72];        // frames, tiled
__device__ __half         g_hhT[2][3][16][32][72];     // h (fp16), tiled per kb
__device__ float          g_hf[2][3][NB][HID];         // fp32 h for decoder
__device__ float          g_c[3][NB][HID];
__device__ float          g_bs[3][G4];
__device__ float          g_bsM[G4];
__device__ unsigned       g_bar;

// perm within 16-byte group so a thread's fp8 fragment is one LDS.u32
__device__ __forceinline__ int perm8(int k) {
    int g = k >> 4, i = k & 15;
    return (g << 4) | (((i & 7) >> 1) << 2) | (((i >> 3) & 1) << 1) | (i & 1);
}

// ---------------- asm helpers ----------------
__device__ __forceinline__ unsigned sptr(const void* p) {
    return (unsigned)__cvta_generic_to_shared(p);
}
__device__ __forceinline__ void bulkcp(unsigned dst, const void* src, unsigned bytes,
                                       unsigned mbar) {
    asm volatile(
        "cp.async.bulk.shared::cluster.global.mbarrier::complete_tx::bytes "
        "[%0], [%1], %2, [%3];"
        :: "r"(dst), "l"(src), "r"(bytes), "r"(mbar) : "memory");
}
__device__ __forceinline__ void mbar_init(unsigned a, unsigned cnt) {
    asm volatile("mbarrier.init.shared.b64 [%0], %1;" :: "r"(a), "r"(cnt) : "memory");
}
__device__ __forceinline__ void mbar_expect(unsigned a, unsigned tx) {
    asm volatile("mbarrier.arrive.expect_tx.shared.b64 _, [%0], %1;"
                 :: "r"(a), "r"(tx) : "memory");
}
__device__ __forceinline__ void mbar_arrive(unsigned a) {
    asm volatile("mbarrier.arrive.shared.b64 _, [%0];" :: "r"(a) : "memory");
}
__device__ __forceinline__ void mbar_wait(unsigned a, unsigned par) {
    asm volatile(
        "{\n\t.reg .pred P;\n\t"
        "W_%=:\n\t"
        "mbarrier.try_wait.parity.acquire.cta.shared::cta.b64 P, [%0], %1, 0x989680;\n\t"
        "@P bra.uni D_%=;\n\t"
        "bra.uni W_%=;\n\t"
        "D_%=:\n\t}"
        :: "r"(a), "r"(par) : "memory");
}
__device__ __forceinline__ void fence_async() {
    asm volatile("fence.proxy.async.shared::cta;" ::: "memory");
}
__device__ __forceinline__ void ldmA4(unsigned a[4], unsigned addr) {
    asm volatile("ldmatrix.sync.aligned.m8n8.x4.shared.b16 {%0,%1,%2,%3}, [%4];"
                 : "=r"(a[0]), "=r"(a[1]), "=r"(a[2]), "=r"(a[3]) : "r"(addr));
}
__device__ __forceinline__ void ldmB2(unsigned b[2], unsigned addr) {
    asm volatile("ldmatrix.sync.aligned.m8n8.x2.shared.b16 {%0,%1}, [%2];"
                 : "=r"(b[0]), "=r"(b[1]) : "r"(addr));
}
__device__ __forceinline__ void mma16816(float c[4], const unsigned a[4], const unsigned b[2]) {
    asm volatile("mma.sync.aligned.m16n8k16.row.col.f32.f16.f16.f32 "
                 "{%0,%1,%2,%3}, {%4,%5,%6,%7}, {%8,%9}, {%0,%1,%2,%3};"
                 : "+f"(c[0]), "+f"(c[1]), "+f"(c[2]), "+f"(c[3])
                 : "r"(a[0]), "r"(a[1]), "r"(a[2]), "r"(a[3]), "r"(b[0]), "r"(b[1]));
}
__device__ __forceinline__ unsigned cvt8x2(unsigned short v) {
    unsigned r;
    asm("cvt.rn.f16x2.e4m3x2 %0, %1;" : "=r"(r) : "h"(v));
    return r;
}
__device__ __forceinline__ float sigm(float x) { return 1.0f / (1.0f + __expf(-x)); }
__device__ __forceinline__ int growf(int n, int j0) { return ((n >> 5) << 10) + j0 + (n & 31); }

// ---------------- grid barrier ----------------
__device__ __forceinline__ void gridbar() {
    __syncthreads();
    if (threadIdx.x == 0) {
        __threadfence();
        unsigned gen = atomicAdd(&g_bar, 1u);
        unsigned target = gen - (gen % NBLK) + NBLK;
        while (*(volatile unsigned*)&g_bar < target) { }
        __threadfence();
    }
    __syncthreads();
}

// ---------------- decoder core (256-thread block) ----------------
__device__ void dec_core(float* smf, int db, int tid,
                         const float* __restrict__ h2, const float* __restrict__ wdec,
                         const float* __restrict__ bdec, float* __restrict__ outp, int toff)
{
    float* sh2 = smf;
    float* sWd = smf + 32 * 257;
    const int o0 = db * 4;
    const int oo = tid & 3, b = (tid >> 2) & 31;
    float acc = 0.0f;
    for (int k0 = 0; k0 < HID; k0 += 256) {
        __syncthreads();
        for (int li = tid; li < 8192; li += 256) {
            int r = li >> 8, c = li & 255;
            sh2[r * 257 + c] = h2[r * HID + k0 + c];
        }
        for (int li = tid; li < 1024; li += 256) {
            int r = li >> 8, c = li & 255;
            sWd[r * 257 + c] = wdec[(o0 + r) * HID + k0 + c];
        }
        __syncthreads();
        if (tid < 128) {
#pragma unroll 8
            for (int k = 0; k < 256; k++)
                acc += sh2[b * 257 + k] * sWd[oo * 257 + k];
        }
    }
    if (tid < 128)
        outp[b * OUTW + toff + o0 + oo] = acc + bdec[o0 + oo];
}

// ---------------- prep 1: build all tiled operands ----------------
__global__ void k_prep1(
    const float* __restrict__ wih1, const float* __restrict__ whh1,
    const float* __restrict__ wih2, const float* __restrict__ whh2,
    const float* __restrict__ wih3, const float* __restrict__ whh3,
    const float* __restrict__ seq,
    const float* __restrict__ bi1, const float* __restrict__ bh1,
    const float* __restrict__ bi2, const float* __restrict__ bh2,
    const float* __restrict__ bi3, const float* __restrict__ bh3)
{
    const long i0 = (long)blockIdx.x * blockDim.x + threadIdx.x;
    const long stride = (long)gridDim.x * blockDim.x;

    // A) weight tiles m=0..4 data + all fp16 pads (m=0..5)
    for (long i = i0; i < 6L * 32 * 16 * 128 * 72; i += stride) {
        int cc = (int)(i % 72); long t1 = i / 72;
        int tr = (int)(t1 % 128); long t2 = t1 / 128;
        int kb = (int)(t2 % 16); long t3 = t2 / 16;
        int jbb = (int)(t3 % 32);
        int m = (int)(t3 / 32);
        if (cc >= 64) { g_WT[m][jbb][kb][tr][cc] = __float2half_rn(0.0f); continue; }
        if (m == 5) continue;   // Mw data filled by k_mw
        const float* p = (m == 0) ? whh1 : (m == 1) ? wih2 : (m == 2) ? whh2
                                 : (m == 3) ? wih3 : whh3;
        int row = ((tr >> 5) << 10) + jbb * 32 + (tr & 31);
        int k = kb * 64 + cc;
        float v = p[(long)row * HID + k];
        __half hi = __float2half_rn(v);
        g_WT[m][jbb][kb][tr][cc] = hi;
        unsigned char* w8 = &g_W8T[m][jbb][kb][0][0];
        w8[tr * 80 + perm8(cc)] =
            __nv_cvt_float_to_fp8((v - __half2float(hi)) * LO_SCALE,
                                  __NV_SATFINITE, __NV_E4M3);
    }
    // B) fp8 row pads (bytes 64..79)
    for (long i = i0; i < 6L * 32 * 16 * 128 * 16; i += stride) {
        int pb = (int)(i % 16); long t1 = i / 16;
        int tr = (int)(t1 % 128); long t2 = t1 / 128;
        int kb = (int)(t2 % 16); long t3 = t2 / 16;
        int jbb = (int)(t3 % 32); int m = (int)(t3 / 32);
        unsigned char* w8 = &g_W8T[m][jbb][kb][0][0];
        w8[tr * 80 + 64 + pb] = 0;
    }
    // C) W1 tiles (K padded 132->192)
    for (long i = i0; i < 32L * 3 * 128 * 72; i += stride) {
        int cc = (int)(i % 72); long t1 = i / 72;
        int tr = (int)(t1 % 128); long t2 = t1 / 128;
        int kb = (int)(t2 % 3); int jbb = (int)(t2 / 3);
        if (cc >= 64) { g_W1T[jbb][kb][tr][cc] = __float2half_rn(0.0f); continue; }
        int row = ((tr >> 5) << 10) + jbb * 32 + (tr & 31);
        int k = kb * 64 + cc;
        float v = (k < IND) ? wih1[(long)row * IND + k] : 0.0f;
        __half hi = __float2half_rn(v);
        g_W1T[jbb][kb][tr][cc] = hi;
        unsigned char* w8 = &g_W18T[jbb][kb][0][0];
        w8[tr * 80 + perm8(cc)] =
            __nv_cvt_float_to_fp8((v - __half2float(hi)) * LO_SCALE,
                                  __NV_SATFINITE, __NV_E4M3);
    }
    for (long i = i0; i < 32L * 3 * 128 * 16; i += stride) {
        int pb = (int)(i % 16); long t1 = i / 16;
        int tr = (int)(t1 % 128); long t2 = t1 / 128;
        int kb = (int)(t2 % 3); int jbb = (int)(t2 / 3);
        unsigned char* w8 = &g_W18T[jbb][kb][0][0];
        w8[tr * 80 + 64 + pb] = 0;
    }
    // D) frames tiled (fp16 hi only)
    for (long i = i0; i < (long)NT * 3 * 32 * 72; i += stride) {
        int cc = (int)(i % 72); long t1 = i / 72;
        int b = (int)(t1 % 32); long t2 = t1 / 32;
        int kb = (int)(t2 % 3); int t = (int)(t2 / 3);
        float v = 0.0f;
        if (cc < 64) {
            int k = kb * 64 + cc;
            if (k < IND) v = seq[((long)b * NT + t) * IND + k];
        }
        g_xhT[t][kb][b][cc] = __float2half_rn(v);
    }
    // E) biases
    for (long i = i0; i < 3L * G4; i += stride) {
        int l = (int)(i >> 12), r = (int)(i & 4095);
        const float* pi = (l == 0) ? bi1 : (l == 1) ? bi2 : bi3;
        const float* ph = (l == 0) ? bh1 : (l == 1) ? bh2 : bh3;
        g_bs[l][r] = pi[r] + ph[r];
    }
    // F) zero state
    for (long i = i0; i < 3L * NB * HID; i += stride) (&g_c[0][0][0])[i] = 0.0f;
    for (long i = i0; i < 2L * 3 * NB * HID; i += stride) (&g_hf[0][0][0][0])[i] = 0.0f;
    for (long i = i0; i < 2L * 3 * 16 * 32 * 72; i += stride)
        (&g_hhT[0][0][0][0][0])[i] = __float2half_rn(0.0f);
}

// ---------------- prep 2: Mw = W_ih1 @ W_dec (tiled out) + bsM ----------------
__global__ void k_mw(const float* __restrict__ wih1, const float* __restrict__ wdec,
                     const float* __restrict__ bdec)
{
    extern __shared__ __align__(16) char smraw[];
    const int tid = threadIdx.x, bid = blockIdx.x;

    if (bid >= 512) {
        int r = (bid - 512) * 256 + tid;
        float a = 0.0f;
        for (int j = 0; j < IND; j++) a += wih1[r * IND + j] * bdec[j];
        g_bsM[r] = g_bs[0][r] + a;
        return;
    }
    float* sW1 = (float*)smraw;              // [128][133]
    float* sWd = (float*)smraw + 128 * 133;  // [132][64]
    const int r0 = (bid >> 4) * 128;
    const int c0 = (bid & 15) * 64;

    for (int li = tid; li < 128 * IND; li += 256) {
        int rr = li / IND, jj = li % IND;
        sW1[rr * 133 + jj] = wih1[(r0 + rr) * IND + jj];
    }
    for (int li = tid; li < IND * 64; li += 256) {
        int j = li >> 6, cc = li & 63;
        sWd[j * 64 + cc] = wdec[j * HID + c0 + cc];
    }
    __syncthreads();

    const int ty = tid >> 4, tx = tid & 15;
    float a[8][4];
#pragma unroll
    for (int i = 0; i < 8; i++)
#pragma unroll
        for (int q = 0; q < 4; q++) a[i][q] = 0.0f;

    for (int j = 0; j < IND; j++) {
        float4 wd = *(const float4*)&sWd[j * 64 + tx * 4];
#pragma unroll
        for (int i = 0; i < 8; i++) {
            float w1 = sW1[(ty + 16 * i) * 133 + j];
            a[i][0] += w1 * wd.x; a[i][1] += w1 * wd.y;
            a[i][2] += w1 * wd.z; a[i][3] += w1 * wd.w;
        }
    }
#pragma unroll
    for (int i = 0; i < 8; i++)
#pragma unroll
        for (int q = 0; q < 4; q++) {
            int r = r0 + ty + 16 * i, c = c0 + tx * 4 + q;
            float v = a[i][q];
            __half hi = __float2half_rn(v);
            int gate = r >> 10, win = r & 1023;
            int jbb = win >> 5, tr = gate * 32 + (win & 31);
            int kb = c >> 6, cc = c & 63;
            g_WT[5][jbb][kb][tr][cc] = hi;
            unsigned char* w8 = &g_W8T[5][jbb][kb][0][0];
            w8[tr * 80 + perm8(cc)] =
                __nv_cvt_float_to_fp8((v - __half2float(hi)) * LO_SCALE,
                                      __NV_SATFINITE, __NV_E4M3);
        }
}

// ---------------- persistent kernel: all 100 steps ----------------
__global__ void __launch_bounds__(256, 1)
k_all(const float* __restrict__ wdec, const float* __restrict__ bdec,
      float* __restrict__ dout)
{
    extern __shared__ __align__(16) char smraw[];
    const int tid = threadIdx.x, bid = blockIdx.x;

    if (bid >= 96) {   // ---- decoder blocks ----
        const int db = bid - 96;
        for (int t = 0; t < NT; t++) {
            if (t > 0)
                dec_core((float*)smraw, db, tid, &g_hf[(t & 1) ^ 1][2][0][0],
                         wdec, bdec, dout, (t - 1) * IND);
            gridbar();
        }
        dec_core((float*)smraw, db, tid, &g_hf[1][2][0][0], wdec, bdec, dout, 99 * IND);
        return;
    }

    // ---- gate blocks ----
    const int l = bid >> 5, jb = bid & 31, j0 = jb << 5;
    const int lane = tid & 31, w = tid >> 5;
    const unsigned smb = sptr(smraw);
    const unsigned fullB = smb + CTRL;        // 4 x 8B
    const unsigned emptyB = smb + CTRL + 32;  // 4 x 8B

    if (tid == 0) {
        for (int s = 0; s < 4; s++) { mbar_init(fullB + s * 8, 1); mbar_init(emptyB + s * 8, 8); }
    }
    fence_async();
    __syncthreads();

    int sg = 0;
    for (int t = 0; t < NT; t++) {
        const int prev = (t & 1) ^ 1, cur = t & 1;
        const int gt = (t % 10) < 5;

        const char *Wt0, *Wt1, *W8t0, *W8t1, *Aht0, *Aht1;
        int nst1;
        if (l == 0) {
            if (gt) {
                Wt0 = (const char*)&g_W1T[jb][0][0][0];  W8t0 = (const char*)&g_W18T[jb][0][0][0];
                Aht0 = (const char*)&g_xhT[t][0][0][0];
                nst1 = 3;
            } else {
                Wt0 = (const char*)&g_WT[5][jb][0][0][0];
                W8t0 = (const char*)&g_W8T[5][jb][0][0][0];
                Aht0 = (const char*)&g_hhT[prev][2][0][0][0];
                nst1 = 16;
            }
            Wt1 = (const char*)&g_WT[0][jb][0][0][0]; W8t1 = (const char*)&g_W8T[0][jb][0][0][0];
            Aht1 = (const char*)&g_hhT[prev][0][0][0][0];
        } else if (l == 1) {
            Wt0 = (const char*)&g_WT[1][jb][0][0][0]; W8t0 = (const char*)&g_W8T[1][jb][0][0][0];
            Aht0 = (const char*)&g_hhT[prev][0][0][0][0];
            Wt1 = (const char*)&g_WT[2][jb][0][0][0]; W8t1 = (const char*)&g_W8T[2][jb][0][0][0];
            Aht1 = (const char*)&g_hhT[prev][1][0][0][0];
            nst1 = 16;
        } else {
            Wt0 = (const char*)&g_WT[3][jb][0][0][0]; W8t0 = (const char*)&g_W8T[3][jb][0][0][0];
            Aht0 = (const char*)&g_hhT[prev][1][0][0][0];
            Wt1 = (const char*)&g_WT[4][jb][0][0][0]; W8t1 = (const char*)&g_W8T[4][jb][0][0][0];
            Aht1 = (const char*)&g_hhT[prev][2][0][0][0];
            nst1 = 16;
        }
        const int nst = nst1 + 16;

        auto refill = [&](int g) {
            const int slot = g & 3, u = g >> 2;
            if (u > 0) mbar_wait(emptyB + slot * 8, (u - 1) & 1);
            const int ls = g - sg;
            const int seg = (ls >= nst1);
            const int kb = seg ? (ls - nst1) : ls;
            const unsigned d = smb + slot * SLOT;
            const unsigned fb = fullB + slot * 8;
            mbar_expect(fb, TXB);
            bulkcp(d + OF_WH, (seg ? Wt1 : Wt0) + (long)kb * TILE_WH, TILE_WH, fb);
            bulkcp(d + OF_W8, (seg ? W8t1 : W8t0) + (long)kb * TILE_W8, TILE_W8, fb);
            bulkcp(d + OF_AH, (seg ? Aht1 : Aht0) + (long)kb * TILE_A, TILE_A, fb);
        };

        float accH[2][2][4], accL[2][2][4];
#pragma unroll
        for (int a = 0; a < 2; a++)
#pragma unroll
            for (int b = 0; b < 2; b++)
#pragma unroll
                for (int c = 0; c < 4; c++) { accH[a][b][c] = 0.0f; accL[a][b][c] = 0.0f; }

        if (tid == 0) { refill(sg); refill(sg + 1); refill(sg + 2); }

        for (int s = 0; s < nst; s++) {
            const int g = sg + s, slot = g & 3;
            if (tid == 0 && s + 3 < nst) refill(g + 3);
            mbar_wait(fullB + slot * 8, (g >> 2) & 1);

            const char* sb = smraw + slot * SLOT;
            const __half* Abh = (const __half*)(sb + OF_AH);
            const __half* Bbh = (const __half*)(sb + OF_WH);
            const unsigned char* Bb8 = (const unsigned char*)(sb + OF_W8);

#pragma unroll
            for (int kk = 0; kk < 64; kk += 16) {
                unsigned ah0[4], ah1[4];
                const int aoff = (lane & 15) * 72 + kk + ((lane >> 4) << 3);
                ldmA4(ah0, sptr(Abh + aoff));
                ldmA4(ah1, sptr(Abh + 16 * 72 + aoff));
#pragma unroll
                for (int nf = 0; nf < 2; nf++) {
                    unsigned bh[2], bl[2];
                    const int boff = ((w << 4) + (nf << 3) + (lane & 7)) * 72 +
                                     kk + (((lane >> 3) & 1) << 3);
                    ldmB2(bh, sptr(Bbh + boff));
                    unsigned u = *(const unsigned*)(Bb8 +
                                  ((w << 4) + (nf << 3) + (lane >> 2)) * 80 +
                                  kk + ((lane & 3) << 2));
                    bl[0] = cvt8x2((unsigned short)(u & 0xffffu));
                    bl[1] = cvt8x2((unsigned short)(u >> 16));
                    mma16816(accH[0][nf], ah0, bh);
                    mma16816(accH[1][nf], ah1, bh);
                    mma16816(accL[0][nf], ah0, bl);
                    mma16816(accL[1][nf], ah1, bl);
                }
            }
            if (lane == 0) mbar_arrive(emptyB + slot * 8);
        }
        __syncthreads();   // all warps done with smem before G staging

        // ---- epilogue: gates -> smem -> pointwise ----
        float* G = (float*)smraw;   // [32][129] fp32, fits in slot0 Wh area
#pragma unroll
        for (int mi = 0; mi < 2; mi++)
#pragma unroll
            for (int nf = 0; nf < 2; nf++)
#pragma unroll
                for (int r = 0; r < 4; r++) {
                    int m = mi * 16 + (lane >> 2) + ((r >> 1) << 3);
                    int n = (w << 4) + (nf << 3) + ((lane & 3) << 1) + (r & 1);
                    int row = growf(n, j0);
                    float bias = (l == 0 && !gt) ? g_bsM[row] : g_bs[l][row];
                    G[m * 129 + n] = accH[mi][nf][r] + accL[mi][nf][r] * LO_I + bias;
                }
        __syncthreads();

        {
            const int b = tid >> 3;
            const int jj0 = (tid & 7) << 2;
#pragma unroll
            for (int q = 0; q < 4; q++) {
                const int jj = jj0 + q, j = j0 + jj;
                float gi = G[b * 129 + jj];
                float gf = G[b * 129 + 32 + jj];
                float gg = G[b * 129 + 64 + jj];
                float go = G[b * 129 + 96 + jj];
                float c0 = g_c[l][b][j];
                float cn = sigm(gf) * c0 + sigm(gi) * tanhf(gg);
                float hn = sigm(go) * tanhf(cn);
                g_c[l][b][j] = cn;
                g_hf[cur][l][b][j] = hn;
                const int kb = j >> 6, cc = j & 63;
                g_hhT[cur][l][kb][b][cc] = __float2half_rn(hn);
            }
        }
        sg += nst;
        gridbar();
    }
}

// ---------------- host ----------------
#define MW_SMEM 101888

extern "C" void kernel_launch(void* const* d_in, const int* in_sizes, int n_in,
                              void* d_out, int out_size) {
    (void)in_sizes; (void)n_in; (void)out_size;
    const float* seq  = (const float*)d_in[0];
    const float* Wih1 = (const float*)d_in[1];
    const float* Whh1 = (const float*)d_in[2];
    const float* bih1 = (const float*)d_in[3];
    const float* bhh1 = (const float*)d_in[4];
    const float* Wih2 = (const float*)d_in[5];
    const float* Whh2 = (const float*)d_in[6];
    const float* bih2 = (const float*)d_in[7];
    const float* bhh2 = (const float*)d_in[8];
    const float* Wih3 = (const float*)d_in[9];
    const float* Whh3 = (const float*)d_in[10];
    const float* bih3 = (const float*)d_in[11];
    const float* bhh3 = (const float*)d_in[12];
    const float* Wdec = (const float*)d_in[13];
    const float* bdec = (const float*)d_in[14];
    float* out = (float*)d_out;

    cudaFuncSetAttribute(k_all, cudaFuncAttributeMaxDynamicSharedMemorySize, SMEM_ALL);
    cudaFuncSetAttribute(k_mw, cudaFuncAttributeMaxDynamicSharedMemorySize, MW_SMEM);

    k_prep1<<<2048, 256>>>(Wih1, Whh1, Wih2, Whh2, Wih3, Whh3, seq,
                           bih1, bhh1, bih2, bhh2, bih3, bhh3);
    k_mw<<<528, 256, MW_SMEM>>>(Wih1, Wdec, bdec);
    k_all<<<NBLK, 256, SMEM_ALL>>>(Wdec, bdec, out);
}

// round 12
// speedup vs baseline: 1.4377x; 1.0004x over previous
#include <cuda_runtime.h>
#include <cuda_fp16.h>
#include <cuda_fp8.h>
#include <math.h>

#define HID   1024
#define G4    4096
#define NB    32
#define NT    100
#define IND   132
#define OUTW  13200
#define NBLK  129
#define NTHR  288
#define LO_SCALE 16384.0f
#define LO_I     (1.0f/16384.0f)

// K=128 stage tiles (bytes)
#define TILE_WH 34816   // 128 rows x 136 halves fp16
#define TILE_W8 18432   // 128 rows x 144 bytes fp8
#define TILE_A  8704    // 32 rows x 136 halves fp16
#define SLOT    61952
#define OF_W8   34816
#define OF_AH   53248
#define DEPTH   3
#define CTRL    185856  // 3*SLOT
#define SMEM_ALL 185920
#define TXB     61952

// ---------------- persistent device scratch (pre-tiled, K=128 tiles) ----------------
// weight tiles: [matrix][jb][kb][row 128][136]  row = gate*32 + r, col = kb*128 + c
// matrices: 0 Whh1, 1 Wih2, 2 Whh2, 3 Wih3, 4 Whh3, 5 Mw(=Wih1@Wdec)
__device__ __half         g_WT[6][32][8][128][136];
__device__ unsigned char  g_W8T[6][32][8][128][144];  // fp8 e4m3 lo * 2^14, perm8 layout
__device__ __half         g_W1T[32][2][128][136];     // Wih1 padded to K=256
__device__ unsigned char  g_W18T[32][2][128][144];
__device__ __half         g_xhT[NT][2][32][136];      // frames, tiled
__device__ __half         g_hhT[2][3][8][32][136];    // h (fp16), tiled per kb
__device__ float          g_hf[2][3][NB][HID];        // fp32 h for decoder
__device__ float          g_c[3][NB][HID];
__device__ float          g_bs[3][G4];
__device__ float          g_bsM[G4];
__device__ unsigned       g_bar;

// perm within 16-byte group so a thread's fp8 fragment is one LDS.u32
__device__ __forceinline__ int perm8(int k) {
    int g = k >> 4, i = k & 15;
    return (g << 4) | (((i & 7) >> 1) << 2) | (((i >> 3) & 1) << 1) | (i & 1);
}

// ---------------- asm helpers ----------------
__device__ __forceinline__ unsigned sptr(const void* p) {
    return (unsigned)__cvta_generic_to_shared(p);
}
__device__ __forceinline__ void bulkcp(unsigned dst, const void* src, unsigned bytes,
                                       unsigned mbar) {
    asm volatile(
        "cp.async.bulk.shared::cluster.global.mbarrier::complete_tx::bytes "
        "[%0], [%1], %2, [%3];"
        :: "r"(dst), "l"(src), "r"(bytes), "r"(mbar) : "memory");
}
__device__ __forceinline__ void mbar_init(unsigned a, unsigned cnt) {
    asm volatile("mbarrier.init.shared.b64 [%0], %1;" :: "r"(a), "r"(cnt) : "memory");
}
__device__ __forceinline__ void mbar_expect(unsigned a, unsigned tx) {
    asm volatile("mbarrier.arrive.expect_tx.shared.b64 _, [%0], %1;"
                 :: "r"(a), "r"(tx) : "memory");
}
__device__ __forceinline__ void mbar_arrive(unsigned a) {
    asm volatile("mbarrier.arrive.shared.b64 _, [%0];" :: "r"(a) : "memory");
}
__device__ __forceinline__ void mbar_wait(unsigned a, unsigned par) {
    asm volatile(
        "{\n\t.reg .pred P;\n\t"
        "W_%=:\n\t"
        "mbarrier.try_wait.parity.acquire.cta.shared::cta.b64 P, [%0], %1, 0x989680;\n\t"
        "@P bra.uni D_%=;\n\t"
        "bra.uni W_%=;\n\t"
        "D_%=:\n\t}"
        :: "r"(a), "r"(par) : "memory");
}
__device__ __forceinline__ void fence_async() {
    asm volatile("fence.proxy.async.shared::cta;" ::: "memory");
}
__device__ __forceinline__ void ldmA4(unsigned a[4], unsigned addr) {
    asm volatile("ldmatrix.sync.aligned.m8n8.x4.shared.b16 {%0,%1,%2,%3}, [%4];"
                 : "=r"(a[0]), "=r"(a[1]), "=r"(a[2]), "=r"(a[3]) : "r"(addr));
}
__device__ __forceinline__ void ldmB2(unsigned b[2], unsigned addr) {
    asm volatile("ldmatrix.sync.aligned.m8n8.x2.shared.b16 {%0,%1}, [%2];"
                 : "=r"(b[0]), "=r"(b[1]) : "r"(addr));
}
__device__ __forceinline__ void mma16816(float c[4], const unsigned a[4], const unsigned b[2]) {
    asm volatile("mma.sync.aligned.m16n8k16.row.col.f32.f16.f16.f32 "
                 "{%0,%1,%2,%3}, {%4,%5,%6,%7}, {%8,%9}, {%0,%1,%2,%3};"
                 : "+f"(c[0]), "+f"(c[1]), "+f"(c[2]), "+f"(c[3])
                 : "r"(a[0]), "r"(a[1]), "r"(a[2]), "r"(a[3]), "r"(b[0]), "r"(b[1]));
}
__device__ __forceinline__ unsigned cvt8x2(unsigned short v) {
    unsigned r;
    asm("cvt.rn.f16x2.e4m3x2 %0, %1;" : "=r"(r) : "h"(v));
    return r;
}
__device__ __forceinline__ float sigm(float x) { return 1.0f / (1.0f + __expf(-x)); }
__device__ __forceinline__ int growf(int n, int j0) { return ((n >> 5) << 10) + j0 + (n & 31); }

// ---------------- grid barrier ----------------
__device__ __forceinline__ void gridbar() {
    __syncthreads();
    if (threadIdx.x == 0) {
        __threadfence();
        unsigned gen = atomicAdd(&g_bar, 1u);
        unsigned target = gen - (gen % NBLK) + NBLK;
        while (*(volatile unsigned*)&g_bar < target) { }
        __threadfence();
    }
    __syncthreads();
}

// ---------------- decoder core (288-thread block) ----------------
__device__ void dec_core(float* smf, int db, int tid,
                         const float* __restrict__ h2, const float* __restrict__ wdec,
                         const float* __restrict__ bdec, float* __restrict__ outp, int toff)
{
    float* sh2 = smf;
    float* sWd = smf + 32 * 257;
    const int o0 = db * 4;
    const int oo = tid & 3, b = (tid >> 2) & 31;
    float acc = 0.0f;
    for (int k0 = 0; k0 < HID; k0 += 256) {
        __syncthreads();
        for (int li = tid; li < 8192; li += NTHR) {
            int r = li >> 8, c = li & 255;
            sh2[r * 257 + c] = h2[r * HID + k0 + c];
        }
        for (int li = tid; li < 1024; li += NTHR) {
            int r = li >> 8, c = li & 255;
            sWd[r * 257 + c] = wdec[(o0 + r) * HID + k0 + c];
        }
        __syncthreads();
        if (tid < 128) {
#pragma unroll 8
            for (int k = 0; k < 256; k++)
                acc += sh2[b * 257 + k] * sWd[oo * 257 + k];
        }
    }
    if (tid < 128)
        outp[b * OUTW + toff + o0 + oo] = acc + bdec[o0 + oo];
}

// ---------------- prep 1: build all tiled operands ----------------
__global__ void k_prep1(
    const float* __restrict__ wih1, const float* __restrict__ whh1,
    const float* __restrict__ wih2, const float* __restrict__ whh2,
    const float* __restrict__ wih3, const float* __restrict__ whh3,
    const float* __restrict__ seq,
    const float* __restrict__ bi1, const float* __restrict__ bh1,
    const float* __restrict__ bi2, const float* __restrict__ bh2,
    const float* __restrict__ bi3, const float* __restrict__ bh3)
{
    const long i0 = (long)blockIdx.x * blockDim.x + threadIdx.x;
    const long stride = (long)gridDim.x * blockDim.x;

    // A) fp16 weight tiles m=0..5 (data m=0..4; pads for all incl m=5)
    for (long i = i0; i < 6L * 32 * 8 * 128 * 136; i += stride) {
        int cc = (int)(i % 136); long t1 = i / 136;
        int tr = (int)(t1 % 128); long t2 = t1 / 128;
        int kb = (int)(t2 % 8); long t3 = t2 / 8;
        int jbb = (int)(t3 % 32);
        int m = (int)(t3 / 32);
        if (cc >= 128) { g_WT[m][jbb][kb][tr][cc] = __float2half_rn(0.0f); continue; }
        if (m == 5) continue;   // Mw data filled by k_mw
        const float* p = (m == 0) ? whh1 : (m == 1) ? wih2 : (m == 2) ? whh2
                                 : (m == 3) ? wih3 : whh3;
        int row = ((tr >> 5) << 10) + jbb * 32 + (tr & 31);
        int k = kb * 128 + cc;
        float v = p[(long)row * HID + k];
        __half hi = __float2half_rn(v);
        g_WT[m][jbb][kb][tr][cc] = hi;
        unsigned char* w8 = &g_W8T[m][jbb][kb][0][0];
        w8[tr * 144 + perm8(cc)] =
            __nv_cvt_float_to_fp8((v - __half2float(hi)) * LO_SCALE,
                                  __NV_SATFINITE, __NV_E4M3);
    }
    // B) fp8 row pads (bytes 128..143) for all m
    for (long i = i0; i < 6L * 32 * 8 * 128 * 16; i += stride) {
        int pb = (int)(i % 16); long t1 = i / 16;
        int tr = (int)(t1 % 128); long t2 = t1 / 128;
        int kb = (int)(t2 % 8); long t3 = t2 / 8;
        int jbb = (int)(t3 % 32); int m = (int)(t3 / 32);
        unsigned char* w8 = &g_W8T[m][jbb][kb][0][0];
        w8[tr * 144 + 128 + pb] = 0;
    }
    // C) W1 tiles (K padded 132->256, 2 kb of 128)
    for (long i = i0; i < 32L * 2 * 128 * 136; i += stride) {
        int cc = (int)(i % 136); long t1 = i / 136;
        int tr = (int)(t1 % 128); long t2 = t1 / 128;
        int kb = (int)(t2 % 2); int jbb = (int)(t2 / 2);
        if (cc >= 128) { g_W1T[jbb][kb][tr][cc] = __float2half_rn(0.0f); continue; }
        int row = ((tr >> 5) << 10) + jbb * 32 + (tr & 31);
        int k = kb * 128 + cc;
        float v = (k < IND) ? wih1[(long)row * IND + k] : 0.0f;
        __half hi = __float2half_rn(v);
        g_W1T[jbb][kb][tr][cc] = hi;
        unsigned char* w8 = &g_W18T[jbb][kb][0][0];
        w8[tr * 144 + perm8(cc)] =
            __nv_cvt_float_to_fp8((v - __half2float(hi)) * LO_SCALE,
                                  __NV_SATFINITE, __NV_E4M3);
    }
    for (long i = i0; i < 32L * 2 * 128 * 16; i += stride) {
        int pb = (int)(i % 16); long t1 = i / 16;
        int tr = (int)(t1 % 128); long t2 = t1 / 128;
        int kb = (int)(t2 % 2); int jbb = (int)(t2 / 2);
        unsigned char* w8 = &g_W18T[jbb][kb][0][0];
        w8[tr * 144 + 128 + pb] = 0;
    }
    // D) frames tiled (fp16 hi only)
    for (long i = i0; i < (long)NT * 2 * 32 * 136; i += stride) {
        int cc = (int)(i % 136); long t1 = i / 136;
        int b = (int)(t1 % 32); long t2 = t1 / 32;
        int kb = (int)(t2 % 2); int t = (int)(t2 / 2);
        float v = 0.0f;
        if (cc < 128) {
            int k = kb * 128 + cc;
            if (k < IND) v = seq[((long)b * NT + t) * IND + k];
        }
        g_xhT[t][kb][b][cc] = __float2half_rn(v);
    }
    // E) biases
    for (long i = i0; i < 3L * G4; i += stride) {
        int l = (int)(i >> 12), r = (int)(i & 4095);
        const float* pi = (l == 0) ? bi1 : (l == 1) ? bi2 : bi3;
        const float* ph = (l == 0) ? bh1 : (l == 1) ? bh2 : bh3;
        g_bs[l][r] = pi[r] + ph[r];
    }
    // F) zero state
    for (long i = i0; i < 3L * NB * HID; i += stride) (&g_c[0][0][0])[i] = 0.0f;
    for (long i = i0; i < 2L * 3 * NB * HID; i += stride) (&g_hf[0][0][0][0])[i] = 0.0f;
    for (long i = i0; i < 2L * 3 * 8 * 32 * 136; i += stride)
        (&g_hhT[0][0][0][0][0])[i] = __float2half_rn(0.0f);
}

// ---------------- prep 2: Mw = W_ih1 @ W_dec (tiled out) + bsM ----------------
__global__ void k_mw(const float* __restrict__ wih1, const float* __restrict__ wdec,
                     const float* __restrict__ bdec)
{
    extern __shared__ __align__(16) char smraw[];
    const int tid = threadIdx.x, bid = blockIdx.x;

    if (bid >= 512) {
        int r = (bid - 512) * 256 + tid;
        float a = 0.0f;
        for (int j = 0; j < IND; j++) a += wih1[r * IND + j] * bdec[j];
        g_bsM[r] = g_bs[0][r] + a;
        return;
    }
    float* sW1 = (float*)smraw;              // [128][133]
    float* sWd = (float*)smraw + 128 * 133;  // [132][64]
    const int r0 = (bid >> 4) * 128;
    const int c0 = (bid & 15) * 64;

    for (int li = tid; li < 128 * IND; li += 256) {
        int rr = li / IND, jj = li % IND;
        sW1[rr * 133 + jj] = wih1[(r0 + rr) * IND + jj];
    }
    for (int li = tid; li < IND * 64; li += 256) {
        int j = li >> 6, cc = li & 63;
        sWd[j * 64 + cc] = wdec[j * HID + c0 + cc];
    }
    __syncthreads();

    const int ty = tid >> 4, tx = tid & 15;
    float a[8][4];
#pragma unroll
    for (int i = 0; i < 8; i++)
#pragma unroll
        for (int q = 0; q < 4; q++) a[i][q] = 0.0f;

    for (int j = 0; j < IND; j++) {
        float4 wd = *(const float4*)&sWd[j * 64 + tx * 4];
#pragma unroll
        for (int i = 0; i < 8; i++) {
            float w1 = sW1[(ty + 16 * i) * 133 + j];
            a[i][0] += w1 * wd.x; a[i][1] += w1 * wd.y;
            a[i][2] += w1 * wd.z; a[i][3] += w1 * wd.w;
        }
    }
#pragma unroll
    for (int i = 0; i < 8; i++)
#pragma unroll
        for (int q = 0; q < 4; q++) {
            int r = r0 + ty + 16 * i, c = c0 + tx * 4 + q;
            float v = a[i][q];
            __half hi = __float2half_rn(v);
            int gate = r >> 10, win = r & 1023;
            int jbb = win >> 5, tr = gate * 32 + (win & 31);
            int kb = c >> 7, cc = c & 127;
            g_WT[5][jbb][kb][tr][cc] = hi;
            unsigned char* w8 = &g_W8T[5][jbb][kb][0][0];
            w8[tr * 144 + perm8(cc)] =
                __nv_cvt_float_to_fp8((v - __half2float(hi)) * LO_SCALE,
                                      __NV_SATFINITE, __NV_E4M3);
        }
}

// ---------------- persistent kernel: all 100 steps ----------------
// gate blocks: warps 0..7 = MMA consumers, warp 8 = bulk-copy producer
__global__ void __launch_bounds__(NTHR, 1)
k_all(const float* __restrict__ wdec, const float* __restrict__ bdec,
      float* __restrict__ dout)
{
    extern __shared__ __align__(16) char smraw[];
    const int tid = threadIdx.x, bid = blockIdx.x;

    if (bid >= 96) {   // ---- decoder blocks ----
        const int db = bid - 96;
        for (int t = 0; t < NT; t++) {
            if (t > 0)
                dec_core((float*)smraw, db, tid, &g_hf[(t & 1) ^ 1][2][0][0],
                         wdec, bdec, dout, (t - 1) * IND);
            gridbar();
        }
        dec_core((float*)smraw, db, tid, &g_hf[1][2][0][0], wdec, bdec, dout, 99 * IND);
        return;
    }

    // ---- gate blocks ----
    const int l = bid >> 5, jb = bid & 31, j0 = jb << 5;
    const int lane = tid & 31, w = tid >> 5;     // w: 0..8
    const unsigned smb = sptr(smraw);
    const unsigned fullB = smb + CTRL;           // 3 x 8B
    const unsigned emptyB = smb + CTRL + 24;     // 3 x 8B

    if (tid == 0) {
        for (int s = 0; s < DEPTH; s++) { mbar_init(fullB + s * 8, 1); mbar_init(emptyB + s * 8, 8); }
    }
    fence_async();
    __syncthreads();

    int sg = 0;
    for (int t = 0; t < NT; t++) {
        const int prev = (t & 1) ^ 1, cur = t & 1;
        const int gt = (t % 10) < 5;

        const char *Wt0, *Wt1, *W8t0, *W8t1, *Aht0, *Aht1;
        int nst1;
        if (l == 0) {
            if (gt) {
                Wt0 = (const char*)&g_W1T[jb][0][0][0];  W8t0 = (const char*)&g_W18T[jb][0][0][0];
                Aht0 = (const char*)&g_xhT[t][0][0][0];
                nst1 = 2;
            } else {
                Wt0 = (const char*)&g_WT[5][jb][0][0][0];
                W8t0 = (const char*)&g_W8T[5][jb][0][0][0];
                Aht0 = (const char*)&g_hhT[prev][2][0][0][0];
                nst1 = 8;
            }
            Wt1 = (const char*)&g_WT[0][jb][0][0][0]; W8t1 = (const char*)&g_W8T[0][jb][0][0][0];
            Aht1 = (const char*)&g_hhT[prev][0][0][0][0];
        } else if (l == 1) {
            Wt0 = (const char*)&g_WT[1][jb][0][0][0]; W8t0 = (const char*)&g_W8T[1][jb][0][0][0];
            Aht0 = (const char*)&g_hhT[prev][0][0][0][0];
            Wt1 = (const char*)&g_WT[2][jb][0][0][0]; W8t1 = (const char*)&g_W8T[2][jb][0][0][0];
            Aht1 = (const char*)&g_hhT[prev][1][0][0][0];
            nst1 = 8;
        } else {
            Wt0 = (const char*)&g_WT[3][jb][0][0][0]; W8t0 = (const char*)&g_W8T[3][jb][0][0][0];
            Aht0 = (const char*)&g_hhT[prev][1][0][0][0];
            Wt1 = (const char*)&g_WT[4][jb][0][0][0]; W8t1 = (const char*)&g_W8T[4][jb][0][0][0];
            Aht1 = (const char*)&g_hhT[prev][2][0][0][0];
            nst1 = 8;
        }
        const int nst = nst1 + 8;

        if (w == 8) {
            // ---- producer warp: all bulk copies for this step ----
            if (lane == 0) {
                for (int s = 0; s < nst; s++) {
                    const int g = sg + s;
                    const int slot = g % DEPTH, u = g / DEPTH;
                    if (u > 0) mbar_wait(emptyB + slot * 8, (u - 1) & 1);
                    const int seg = (s >= nst1);
                    const int kb = seg ? (s - nst1) : s;
                    const unsigned d = smb + slot * SLOT;
                    const unsigned fb = fullB + slot * 8;
                    mbar_expect(fb, TXB);
                    bulkcp(d, (seg ? Wt1 : Wt0) + (long)kb * TILE_WH, TILE_WH, fb);
                    bulkcp(d + OF_W8, (seg ? W8t1 : W8t0) + (long)kb * TILE_W8, TILE_W8, fb);
                    bulkcp(d + OF_AH, (seg ? Aht1 : Aht0) + (long)kb * TILE_A, TILE_A, fb);
                }
            }
        } else {
            // ---- consumer warps: MMA ----
            float accH[2][2][4], accL[2][2][4];
#pragma unroll
            for (int a = 0; a < 2; a++)
#pragma unroll
                for (int b = 0; b < 2; b++)
#pragma unroll
                    for (int c = 0; c < 4; c++) { accH[a][b][c] = 0.0f; accL[a][b][c] = 0.0f; }

            for (int s = 0; s < nst; s++) {
                const int g = sg + s, slot = g % DEPTH;
                mbar_wait(fullB + slot * 8, (g / DEPTH) & 1);

                const char* sb = smraw + slot * SLOT;
                const __half* Abh = (const __half*)(sb + OF_AH);
                const __half* Bbh = (const __half*)sb;
                const unsigned char* Bb8 = (const unsigned char*)(sb + OF_W8);

#pragma unroll
                for (int kk = 0; kk < 128; kk += 16) {
                    unsigned ah0[4], ah1[4];
                    const int aoff = (lane & 15) * 136 + kk + ((lane >> 4) << 3);
                    ldmA4(ah0, sptr(Abh + aoff));
                    ldmA4(ah1, sptr(Abh + 16 * 136 + aoff));
#pragma unroll
                    for (int nf = 0; nf < 2; nf++) {
                        unsigned bh[2], bl[2];
                        const int boff = ((w << 4) + (nf << 3) + (lane & 7)) * 136 +
                                         kk + (((lane >> 3) & 1) << 3);
                        ldmB2(bh, sptr(Bbh + boff));
                        unsigned u = *(const unsigned*)(Bb8 +
                                      ((w << 4) + (nf << 3) + (lane >> 2)) * 144 +
                                      kk + ((lane & 3) << 2));
                        bl[0] = cvt8x2((unsigned short)(u & 0xffffu));
                        bl[1] = cvt8x2((unsigned short)(u >> 16));
                        mma16816(accH[0][nf], ah0, bh);
                        mma16816(accH[1][nf], ah1, bh);
                        mma16816(accL[0][nf], ah0, bl);
                        mma16816(accL[1][nf], ah1, bl);
                    }
                }
                if (lane == 0) mbar_arrive(emptyB + slot * 8);
            }

            // stage gates + bias into smem (slot0 region, safe: no pending copies)
            __syncthreads();
            float* G = (float*)smraw;   // [32][129] fp32
#pragma unroll
            for (int mi = 0; mi < 2; mi++)
#pragma unroll
                for (int nf = 0; nf < 2; nf++)
#pragma unroll
                    for (int r = 0; r < 4; r++) {
                        int m = mi * 16 + (lane >> 2) + ((r >> 1) << 3);
                        int n = (w << 4) + (nf << 3) + ((lane & 3) << 1) + (r & 1);
                        int row = growf(n, j0);
                        float bias = (l == 0 && !gt) ? g_bsM[row] : g_bs[l][row];
                        G[m * 129 + n] = accH[mi][nf][r] + accL[mi][nf][r] * LO_I + bias;
                    }
        }
        if (w == 8) __syncthreads();   // producer joins the pre-G barrier
        __syncthreads();

        // ---- pointwise LSTM update (first 256 threads) ----
        if (tid < 256) {
            const int b = tid >> 3;
            const int jj0 = (tid & 7) << 2;
#pragma unroll
            for (int q = 0; q < 4; q++) {
                const int jj = jj0 + q, j = j0 + jj;
                float* G = (float*)smraw;
                float gi = G[b * 129 + jj];
                float gf = G[b * 129 + 32 + jj];
                float gg = G[b * 129 + 64 + jj];
                float go = G[b * 129 + 96 + jj];
                float c0 = g_c[l][b][j];
                float cn = sigm(gf) * c0 + sigm(gi) * tanhf(gg);
                float hn = sigm(go) * tanhf(cn);
                g_c[l][b][j] = cn;
                g_hf[cur][l][b][j] = hn;
                const int kb = j >> 7, cc = j & 127;
                g_hhT[cur][l][kb][b][cc] = __float2half_rn(hn);
            }
        }
        fence_async();   // order generic G writes before next step's bulk copies
        sg += nst;
        gridbar();
    }
}

// ---------------- host ----------------
#define MW_SMEM 101888

extern "C" void kernel_launch(void* const* d_in, const int* in_sizes, int n_in,
                              void* d_out, int out_size) {
    (void)in_sizes; (void)n_in; (void)out_size;
    const float* seq  = (const float*)d_in[0];
    const float* Wih1 = (const float*)d_in[1];
    const float* Whh1 = (const float*)d_in[2];
    const float* bih1 = (const float*)d_in[3];
    const float* bhh1 = (const float*)d_in[4];
    const float* Wih2 = (const float*)d_in[5];
    const float* Whh2 = (const float*)d_in[6];
    const float* bih2 = (const float*)d_in[7];
    const float* bhh2 = (const float*)d_in[8];
    const float* Wih3 = (const float*)d_in[9];
    const float* Whh3 = (const float*)d_in[10];
    const float* bih3 = (const float*)d_in[11];
    const float* bhh3 = (const float*)d_in[12];
    const float* Wdec = (const float*)d_in[13];
    const float* bdec = (const float*)d_in[14];
    float* out = (float*)d_out;

    cudaFuncSetAttribute(k_all, cudaFuncAttributeMaxDynamicSharedMemorySize, SMEM_ALL);
    cudaFuncSetAttribute(k_mw, cudaFuncAttributeMaxDynamicSharedMemorySize, MW_SMEM);

    k_prep1<<<2048, 256>>>(Wih1, Whh1, Wih2, Whh2, Wih3, Whh3, seq,
                           bih1, bhh1, bih2, bhh2, bih3, bhh3);
    k_mw<<<528, 256, MW_SMEM>>>(Wih1, Wdec, bdec);
    k_all<<<NBLK, NTHR, SMEM_ALL>>>(Wdec, bdec, out);
}